// round 13
// baseline (speedup 1.0000x reference)
#include <cuda_runtime.h>
#include <cstdint>

// Problem constants
#define BB      2
#define S_NEW   1024
#define S_CACHE 3072
#define S_TOT   4096
#define NH      16
#define DK      128
#define DM      2048

// Scratch (device globals — no allocation allowed)
__device__ float g_q[BB*NH*S_NEW*DK];    // Q in [b,h,s,d] (tf32-rounded)
__device__ float g_att[BB*S_NEW*DM];     // attention output [b,s,h*dk] (tf32-rounded)
__device__ float g_xr[BB*S_NEW*DM];      // x rounded to tf32
__device__ float g_wr[4*DM*DM];          // Wq,Wk,Wv,Wo rounded to tf32

// ---------------------------------------------------------------------------
// helpers
// ---------------------------------------------------------------------------
__device__ __forceinline__ uint32_t smem_u32(const void* p) {
    uint32_t a;
    asm("{ .reg .u64 t; cvta.to.shared.u64 t, %1; cvt.u32.u64 %0, t; }"
        : "=r"(a) : "l"(p));
    return a;
}
__device__ __forceinline__ void cp16(uint32_t so, const void* gp) {
    asm volatile("cp.async.cg.shared.global [%0], [%1], 16;" :: "r"(so), "l"(gp));
}
__device__ __forceinline__ float rna_tf32(float x) {
    uint32_t u;
    asm("cvt.rna.tf32.f32 %0, %1;" : "=r"(u) : "f"(x));
    return __uint_as_float(u);
}

// D(16x8) += A(16x8,row) * B(8x8,col)  — tf32 tensor-core MMA (baseline PTX)
#define MMA8(c, a, b)                                                          \
    asm volatile("mma.sync.aligned.m16n8k8.row.col.f32.tf32.tf32.f32 "        \
        "{%0,%1,%2,%3}, {%4,%5,%6,%7}, {%8,%9}, {%0,%1,%2,%3};"               \
        : "+f"((c)[0]), "+f"((c)[1]), "+f"((c)[2]), "+f"((c)[3])              \
        : "r"((a)[0]), "r"((a)[1]), "r"((a)[2]), "r"((a)[3]),                 \
          "r"((b)[0]), "r"((b)[1]))

// ---------------------------------------------------------------------------
// 0) Round x and the four weight matrices to tf32 (RNA, unbiased) once.
// ---------------------------------------------------------------------------
__global__ void round_kernel(const float* __restrict__ x,
                             const float* __restrict__ Wq,
                             const float* __restrict__ Wk,
                             const float* __restrict__ Wv,
                             const float* __restrict__ Wo) {
    const int SEG = DM * DM;                 // 4194304
    int i = blockIdx.x * blockDim.x + threadIdx.x;
    const int stride = gridDim.x * blockDim.x;
    for (; i < 5 * SEG; i += stride) {
        int seg = i >> 22, o = i & (SEG - 1);
        float v;
        float* dst;
        if (seg == 0)      { v = x[o];  dst = g_xr + o; }
        else               { const float* W = (seg == 1) ? Wq : (seg == 2) ? Wk
                                              : (seg == 3) ? Wv : Wo;
                             v = W[o]; dst = g_wr + (size_t)(seg - 1) * SEG + o; }
        *dst = rna_tf32(v);
    }
}

// ---------------------------------------------------------------------------
// 1) Copy old cache rows into the updated-cache output region
// ---------------------------------------------------------------------------
__global__ void copy_cache_kernel(const float4* __restrict__ src,
                                  float4* __restrict__ dst) {
    int i = blockIdx.x * blockDim.x + threadIdx.x;
    const int per   = S_CACHE * DK / 4;
    const int total = 2 * BB * NH * per;
    if (i < total) {
        int c = i / per;
        int w = i - c * per;
        dst[(size_t)c * (S_TOT * DK / 4) + w] = src[i];
    }
}

// ---------------------------------------------------------------------------
// 2/4) Tensor-core GEMM (mma.sync tf32): Y[M,N] = A[M,K] @ W[N,K]^T + bias.
// ---------------------------------------------------------------------------
#define KC    16
#define PITCH 20
#define NCH   (DM / KC)          // 128

__global__ __launch_bounds__(256, 2)
void gemm_mma_kernel(const float* __restrict__ B0,
                     const float* __restrict__ B1,
                     const float* __restrict__ B2,
                     float* __restrict__ cache_out,
                     float* __restrict__ outp,
                     int mode) {
    __shared__ __align__(16) float As[2][128 * PITCH];
    __shared__ __align__(16) float Bs[2][128 * PITCH];

    const int tid = threadIdx.x;
    const int warp = tid >> 5, lane = tid & 31;
    const int g = lane >> 2, t = lane & 3;
    const int z = blockIdx.z;

    const float* Ap = mode ? g_att : g_xr;
    const float* W  = g_wr + (size_t)(mode ? 3 : z) * DM * DM;
    const float* bias = mode ? B0 : (z == 0 ? B0 : (z == 1 ? B1 : B2));

    const int m0 = blockIdx.y * 128, n0 = blockIdx.x * 128;
    const int wm = (warp & 1) * 64, wn = (warp >> 1) * 32;

    const uint32_t sA = smem_u32(As);
    const uint32_t sB = smem_u32(Bs);

    float acc[4][4][4];
#pragma unroll
    for (int mt = 0; mt < 4; mt++)
#pragma unroll
        for (int nt = 0; nt < 4; nt++)
#pragma unroll
            for (int r = 0; r < 4; r++) acc[mt][nt][r] = 0.f;

    auto load = [&](int c, int buf) {
        const int k0 = c * KC;
        const uint32_t off = (uint32_t)buf * 128 * PITCH * 4;
#pragma unroll
        for (int i = 0; i < 2; i++) {
            int idx = tid + i * 256;
            int row = idx >> 2, c4 = idx & 3;
            cp16(sA + off + (row * PITCH + c4 * 4) * 4,
                 Ap + (size_t)(m0 + row) * DM + k0 + c4 * 4);
            cp16(sB + off + (row * PITCH + c4 * 4) * 4,
                 W + (size_t)(n0 + row) * DM + k0 + c4 * 4);
        }
        asm volatile("cp.async.commit_group;" ::: "memory");
    };

    load(0, 0);
    load(1, 1);

    for (int c = 0; c < NCH; ++c) {
        if (c + 1 < NCH) asm volatile("cp.async.wait_group 1;" ::: "memory");
        else             asm volatile("cp.async.wait_group 0;" ::: "memory");
        __syncthreads();

        const float* as = As[c & 1];
        const float* bs = Bs[c & 1];
#pragma unroll
        for (int ks = 0; ks < 2; ks++) {
            const int kb = ks * 8;
            uint32_t a[4][4], b[4][2];
#pragma unroll
            for (int mt = 0; mt < 4; mt++) {
                int r = wm + mt * 16 + g;
                a[mt][0] = __float_as_uint(as[r * PITCH + kb + t]);
                a[mt][1] = __float_as_uint(as[(r + 8) * PITCH + kb + t]);
                a[mt][2] = __float_as_uint(as[r * PITCH + kb + t + 4]);
                a[mt][3] = __float_as_uint(as[(r + 8) * PITCH + kb + t + 4]);
            }
#pragma unroll
            for (int nt = 0; nt < 4; nt++) {
                int cn = wn + nt * 8 + g;
                b[nt][0] = __float_as_uint(bs[cn * PITCH + kb + t]);
                b[nt][1] = __float_as_uint(bs[cn * PITCH + kb + t + 4]);
            }
#pragma unroll
            for (int mt = 0; mt < 4; mt++)
#pragma unroll
                for (int nt = 0; nt < 4; nt++)
                    MMA8(acc[mt][nt], a[mt], b[nt]);
        }
        __syncthreads();
        if (c + 2 < NCH) load(c + 2, c & 1);
    }

    const int hh = blockIdx.x;
#pragma unroll
    for (int mt = 0; mt < 4; mt++) {
        int m = m0 + wm + mt * 16 + g;
        int bb = m >> 10, sp = m & 1023;
#pragma unroll
        for (int nt = 0; nt < 4; nt++) {
            int d = wn + nt * 8 + 2 * t;
            int n = n0 + d;
            float b0v = __ldg(bias + n), b1v = __ldg(bias + n + 1);
            float2 v0 = make_float2(acc[mt][nt][0] + b0v, acc[mt][nt][1] + b1v);
            float2 v1 = make_float2(acc[mt][nt][2] + b0v, acc[mt][nt][3] + b1v);
            if (mode) {
                float* dst = outp + (size_t)m * DM + n;
                *(float2*)dst            = v0;
                *(float2*)(dst + 8 * DM) = v1;
            } else if (z == 0) {
                // Q: RNA-round so the attention MMA truncation is unbiased
                v0.x = rna_tf32(v0.x); v0.y = rna_tf32(v0.y);
                v1.x = rna_tf32(v1.x); v1.y = rna_tf32(v1.y);
                float* dst = g_q + ((size_t)(bb * NH + hh) * S_NEW + sp) * DK + d;
                *(float2*)dst            = v0;
                *(float2*)(dst + 8 * DK) = v1;
            } else {
                float* dst = cache_out
                    + ((size_t)(((z - 1) * BB + bb) * NH + hh) * S_TOT
                       + S_CACHE + sp) * DK + d;
                *(float2*)dst            = v0;
                *(float2*)(dst + 8 * DK) = v1;
            }
        }
    }
}

// ---------------------------------------------------------------------------
// 3) Causal flash attention on tensor cores (mma.sync tf32).
//    One block = (b, h, 128-query tile); 8 warps x 16 rows; 64-key tiles.
//    Qs[m][k], Ks[n][k] natural (row.col MMA); Vt[d][j] transposed; Ps[m][j].
// ---------------------------------------------------------------------------
#define FL_SMEM ((128*132 + 64*132 + 128*68 + 128*68) * 4)   // 171008 B

__global__ __launch_bounds__(256, 1)
void flash_mma_kernel(const float* __restrict__ cache_out) {
    extern __shared__ float smf[];
    float* Qs = smf;                    // [128][132]
    float* Ks = Qs + 128 * 132;         // [64][132]
    float* Vt = Ks + 64 * 132;          // [128][68]
    float* Ps = Vt + 128 * 68;          // [128][68]

    const int qt = 7 - (int)blockIdx.x;      // longest tiles first
    const int h  = blockIdx.y;
    const int b  = blockIdx.z;
    const int q0 = qt << 7;
    const int tid  = threadIdx.x;
    const int warp = tid >> 5, lane = tid & 31;
    const int g = lane >> 2, t = lane & 3;
    const int wm = warp << 4;

    const float* Qg = g_q + ((size_t)(b * NH + h) * S_NEW + q0) * DK;
    const float* Kg = cache_out + (size_t)(b * NH + h) * S_TOT * DK;
    const float* Vg = cache_out + (size_t)((BB + b) * NH + h) * S_TOT * DK;

    const uint32_t sQ = smem_u32(Qs), sK = smem_u32(Ks);

    // Q tile via cp.async (128x128)
#pragma unroll
    for (int i = 0; i < 16; i++) {
        int idx = tid + i * 256;         // 0..4095
        int row = idx >> 5, c16 = idx & 31;
        cp16(sQ + (row * 132 + c16 * 4) * 4, Qg + (size_t)row * DK + c16 * 4);
    }
    asm volatile("cp.async.commit_group;" ::: "memory");

    float O[16][4];
    float M[2] = {-1e30f, -1e30f}, L[2] = {0.f, 0.f};
#pragma unroll
    for (int i = 0; i < 16; i++) { O[i][0] = O[i][1] = O[i][2] = O[i][3] = 0.f; }

    const float cs = 0.0883883476483184f * 1.4426950408889634f; // 1/sqrt(128)*log2e
    const int ntiles = 50 + 2 * qt;

    for (int kt = 0; kt < ntiles; ++kt) {
        __syncthreads();                 // prior Ks/Vt fully consumed
        const float* kp = Kg + (size_t)(kt * 64) * DK;
        const float* vp = Vg + (size_t)(kt * 64) * DK;

        // K tile (64x128) natural layout via cp.async
#pragma unroll
        for (int i = 0; i < 8; i++) {
            int idx = tid + i * 256;     // 0..2047
            int row = idx >> 5, c16 = idx & 31;
            cp16(sK + (row * 132 + c16 * 4) * 4, kp + (size_t)row * DK + c16 * 4);
        }
        asm volatile("cp.async.commit_group;" ::: "memory");

        // V transposed: Vt[d][j]. Coalesced LDG.32 per j, STS.128 per d-row.
#pragma unroll
        for (int i = 0; i < 8; i++) {
            int idx = tid + i * 256;     // 0..2047
            int d = idx & 127, j0 = (idx >> 7) << 2;
            float4 v;
            v.x = vp[(size_t)(j0 + 0) * DK + d];
            v.y = vp[(size_t)(j0 + 1) * DK + d];
            v.z = vp[(size_t)(j0 + 2) * DK + d];
            v.w = vp[(size_t)(j0 + 3) * DK + d];
            *(float4*)(Vt + d * 68 + j0) = v;
        }
        asm volatile("cp.async.wait_group 0;" ::: "memory");
        __syncthreads();

        // ---- S = Q @ K^T (warp: 16x64) ----
        float s[8][4];
#pragma unroll
        for (int nt = 0; nt < 8; nt++) { s[nt][0] = s[nt][1] = s[nt][2] = s[nt][3] = 0.f; }
#pragma unroll
        for (int ks = 0; ks < 16; ks++) {
            const int kb = ks * 8;
            uint32_t a[4];
            a[0] = __float_as_uint(Qs[(wm + g) * 132 + kb + t]);
            a[1] = __float_as_uint(Qs[(wm + g + 8) * 132 + kb + t]);
            a[2] = __float_as_uint(Qs[(wm + g) * 132 + kb + t + 4]);
            a[3] = __float_as_uint(Qs[(wm + g + 8) * 132 + kb + t + 4]);
#pragma unroll
            for (int nt = 0; nt < 8; nt++) {
                uint32_t bf[2];
                bf[0] = __float_as_uint(Ks[(nt * 8 + g) * 132 + kb + t]);
                bf[1] = __float_as_uint(Ks[(nt * 8 + g) * 132 + kb + t + 4]);
                MMA8(s[nt], a, bf);
            }
        }

        // ---- online softmax (rows g, g+8 of this warp) ----
        const bool domask = (kt * 64 + 63 >= S_CACHE + q0);
#pragma unroll
        for (int r = 0; r < 2; r++) {
            const int ml = wm + g + 8 * r;       // query row within tile
            float mx = -1e30f;
#pragma unroll
            for (int nt = 0; nt < 8; nt++) {
                float v0 = s[nt][2 * r]     * cs;
                float v1 = s[nt][2 * r + 1] * cs;
                if (domask) {
                    int j = kt * 64 + nt * 8 + 2 * t;
                    if (j     >= S_CACHE + q0 + ml) v0 = -1e30f;
                    if (j + 1 >= S_CACHE + q0 + ml) v1 = -1e30f;
                }
                s[nt][2 * r] = v0; s[nt][2 * r + 1] = v1;
                mx = fmaxf(mx, fmaxf(v0, v1));
            }
            mx = fmaxf(mx, __shfl_xor_sync(0xffffffffu, mx, 1));
            mx = fmaxf(mx, __shfl_xor_sync(0xffffffffu, mx, 2));
            float newM  = fmaxf(M[r], mx);
            float alpha = exp2f(M[r] - newM);
            M[r] = newM;
            float rs = 0.f;
#pragma unroll
            for (int nt = 0; nt < 8; nt++) {
                float p0 = rna_tf32(exp2f(s[nt][2 * r]     - newM));
                float p1 = rna_tf32(exp2f(s[nt][2 * r + 1] - newM));
                rs += p0 + p1;
                *(float2*)(Ps + ml * 68 + nt * 8 + 2 * t) = make_float2(p0, p1);
            }
            rs += __shfl_xor_sync(0xffffffffu, rs, 1);
            rs += __shfl_xor_sync(0xffffffffu, rs, 2);
            L[r] = L[r] * alpha + rs;
#pragma unroll
            for (int dt = 0; dt < 16; dt++) {
                O[dt][2 * r]     *= alpha;
                O[dt][2 * r + 1] *= alpha;
            }
        }
        __syncwarp();

        // ---- O += P @ V (warp: 16x128, k=64) ----
#pragma unroll
        for (int jb = 0; jb < 8; jb++) {
            const int kb = jb * 8;
            uint32_t a[4];
            a[0] = __float_as_uint(Ps[(wm + g) * 68 + kb + t]);
            a[1] = __float_as_uint(Ps[(wm + g + 8) * 68 + kb + t]);
            a[2] = __float_as_uint(Ps[(wm + g) * 68 + kb + t + 4]);
            a[3] = __float_as_uint(Ps[(wm + g + 8) * 68 + kb + t + 4]);
#pragma unroll
            for (int dt = 0; dt < 16; dt++) {
                uint32_t bf[2];
                bf[0] = __float_as_uint(Vt[(dt * 8 + g) * 68 + kb + t]);
                bf[1] = __float_as_uint(Vt[(dt * 8 + g) * 68 + kb + t + 4]);
                MMA8(O[dt], a, bf);
            }
        }
    }

    // epilogue: normalize + RNA-round + write g_att [b,s,h*dk]
#pragma unroll
    for (int r = 0; r < 2; r++) {
        float inv = 1.f / L[r];
        int m = q0 + wm + g + 8 * r;
        float* dst = g_att + (size_t)(b * S_NEW + m) * DM + h * DK;
#pragma unroll
        for (int dt = 0; dt < 16; dt++) {
            float2 v = make_float2(rna_tf32(O[dt][2 * r] * inv),
                                   rna_tf32(O[dt][2 * r + 1] * inv));
            *(float2*)(dst + dt * 8 + 2 * t) = v;
        }
    }
}

// ---------------------------------------------------------------------------
// Launch
// ---------------------------------------------------------------------------
extern "C" void kernel_launch(void* const* d_in, const int* in_sizes, int n_in,
                              void* d_out, int out_size) {
    const float* x     = (const float*)d_in[0];
    const float* cache = (const float*)d_in[1];
    const float* Wq    = (const float*)d_in[2];
    const float* bq    = (const float*)d_in[3];
    const float* Wk    = (const float*)d_in[4];
    const float* bk    = (const float*)d_in[5];
    const float* Wv    = (const float*)d_in[6];
    const float* bv    = (const float*)d_in[7];
    const float* Wo    = (const float*)d_in[8];
    const float* bo    = (const float*)d_in[9];

    float* out       = (float*)d_out;
    float* cache_out = out + (size_t)BB * S_NEW * DM;

    // 0) round x + weights to tf32 (RNA)
    round_kernel<<<4096, 256>>>(x, Wq, Wk, Wv, Wo);

    // 1) copy old cache rows
    {
        int total  = 2 * BB * NH * (S_CACHE * DK / 4);
        int blocks = (total + 255) / 256;
        copy_cache_kernel<<<blocks, 256>>>((const float4*)cache, (float4*)cache_out);
    }

    // 2) fused QKV projections on tensor cores (z=0 Q, z=1 K, z=2 V)
    gemm_mma_kernel<<<dim3(16, 16, 3), 256>>>(bq, bk, bv, cache_out, nullptr, 0);

    // 3) flash attention on tensor cores
    cudaFuncSetAttribute(flash_mma_kernel,
                         cudaFuncAttributeMaxDynamicSharedMemorySize, FL_SMEM);
    flash_mma_kernel<<<dim3(8, NH, BB), 256, FL_SMEM>>>(cache_out);

    // 4) output projection on tensor cores
    gemm_mma_kernel<<<dim3(16, 16, 1), 256>>>(bo, nullptr, nullptr,
                                              nullptr, out, 1);
}

// round 14
// speedup vs baseline: 1.0903x; 1.0903x over previous
#include <cuda_runtime.h>
#include <cstdint>

// Problem constants
#define BB      2
#define S_NEW   1024
#define S_CACHE 3072
#define S_TOT   4096
#define NH      16
#define DK      128
#define DM      2048

// Scratch (device globals — no allocation allowed)
__device__ float g_q[BB*NH*S_NEW*DK];    // Q in [b,h,s,d] (tf32-rounded)
__device__ float g_att[BB*S_NEW*DM];     // attention output [b,s,h*dk] (tf32-rounded)
__device__ float g_xr[BB*S_NEW*DM];      // x rounded to tf32
__device__ float g_wr[4*DM*DM];          // Wq,Wk,Wv,Wo rounded to tf32

// ---------------------------------------------------------------------------
// helpers
// ---------------------------------------------------------------------------
__device__ __forceinline__ uint32_t smem_u32(const void* p) {
    uint32_t a;
    asm("{ .reg .u64 t; cvta.to.shared.u64 t, %1; cvt.u32.u64 %0, t; }"
        : "=r"(a) : "l"(p));
    return a;
}
__device__ __forceinline__ void cp16(uint32_t so, const void* gp) {
    asm volatile("cp.async.cg.shared.global [%0], [%1], 16;" :: "r"(so), "l"(gp));
}
__device__ __forceinline__ float rna_tf32(float x) {
    uint32_t u;
    asm("cvt.rna.tf32.f32 %0, %1;" : "=r"(u) : "f"(x));
    return __uint_as_float(u);
}

// D(16x8) += A(16x8,row) * B(8x8,col)  — tf32 tensor-core MMA (baseline PTX)
#define MMA8(c, a, b)                                                          \
    asm volatile("mma.sync.aligned.m16n8k8.row.col.f32.tf32.tf32.f32 "        \
        "{%0,%1,%2,%3}, {%4,%5,%6,%7}, {%8,%9}, {%0,%1,%2,%3};"               \
        : "+f"((c)[0]), "+f"((c)[1]), "+f"((c)[2]), "+f"((c)[3])              \
        : "r"((a)[0]), "r"((a)[1]), "r"((a)[2]), "r"((a)[3]),                 \
          "r"((b)[0]), "r"((b)[1]))

// ---------------------------------------------------------------------------
// 0) Round x and the four weight matrices to tf32 (RNA, unbiased) once.
// ---------------------------------------------------------------------------
__global__ void round_kernel(const float* __restrict__ x,
                             const float* __restrict__ Wq,
                             const float* __restrict__ Wk,
                             const float* __restrict__ Wv,
                             const float* __restrict__ Wo) {
    const int SEG = DM * DM;                 // 4194304
    int i = blockIdx.x * blockDim.x + threadIdx.x;
    const int stride = gridDim.x * blockDim.x;
    for (; i < 5 * SEG; i += stride) {
        int seg = i >> 22, o = i & (SEG - 1);
        float v;
        float* dst;
        if (seg == 0)      { v = x[o];  dst = g_xr + o; }
        else               { const float* W = (seg == 1) ? Wq : (seg == 2) ? Wk
                                              : (seg == 3) ? Wv : Wo;
                             v = W[o]; dst = g_wr + (size_t)(seg - 1) * SEG + o; }
        *dst = rna_tf32(v);
    }
}

// ---------------------------------------------------------------------------
// 1) Copy old cache rows into the updated-cache output region
// ---------------------------------------------------------------------------
__global__ void copy_cache_kernel(const float4* __restrict__ src,
                                  float4* __restrict__ dst) {
    int i = blockIdx.x * blockDim.x + threadIdx.x;
    const int per   = S_CACHE * DK / 4;
    const int total = 2 * BB * NH * per;
    if (i < total) {
        int c = i / per;
        int w = i - c * per;
        dst[(size_t)c * (S_TOT * DK / 4) + w] = src[i];
    }
}

// ---------------------------------------------------------------------------
// 2/4) Tensor-core GEMM (mma.sync tf32): Y[M,N] = A[M,K] @ W[N,K]^T + bias.
//      128x128 tile, 8 warps (2Mx4N), KC=32, double-buffered cp.async.
// ---------------------------------------------------------------------------
#define KC      32
#define GPITCH  36
#define NCH     (DM / KC)          // 64
#define GM_SMEM (2 * 2 * 128 * GPITCH * 4)   // 73728 B

__global__ __launch_bounds__(256, 2)
void gemm_mma_kernel(const float* __restrict__ B0,
                     const float* __restrict__ B1,
                     const float* __restrict__ B2,
                     float* __restrict__ cache_out,
                     float* __restrict__ outp,
                     int mode) {
    extern __shared__ float gsm[];
    float* As = gsm;                          // [2][128*GPITCH]
    float* Bs = gsm + 2 * 128 * GPITCH;       // [2][128*GPITCH]

    const int tid = threadIdx.x;
    const int warp = tid >> 5, lane = tid & 31;
    const int g = lane >> 2, t = lane & 3;
    const int z = blockIdx.z;

    const float* Ap = mode ? g_att : g_xr;
    const float* W  = g_wr + (size_t)(mode ? 3 : z) * DM * DM;
    const float* bias = mode ? B0 : (z == 0 ? B0 : (z == 1 ? B1 : B2));

    const int m0 = blockIdx.y * 128, n0 = blockIdx.x * 128;
    const int wm = (warp & 1) * 64, wn = (warp >> 1) * 32;

    const uint32_t sA = smem_u32(As);
    const uint32_t sB = smem_u32(Bs);

    float acc[4][4][4];
#pragma unroll
    for (int mt = 0; mt < 4; mt++)
#pragma unroll
        for (int nt = 0; nt < 4; nt++)
#pragma unroll
            for (int r = 0; r < 4; r++) acc[mt][nt][r] = 0.f;

    auto load = [&](int c, int buf) {
        const int k0 = c * KC;
        const uint32_t offA = sA + (uint32_t)buf * 128 * GPITCH * 4;
        const uint32_t offB = sB + (uint32_t)buf * 128 * GPITCH * 4;
#pragma unroll
        for (int i = 0; i < 4; i++) {
            int idx = tid + i * 256;          // 0..1023
            int row = idx >> 3, c4 = idx & 7;
            cp16(offA + (row * GPITCH + c4 * 4) * 4,
                 Ap + (size_t)(m0 + row) * DM + k0 + c4 * 4);
            cp16(offB + (row * GPITCH + c4 * 4) * 4,
                 W + (size_t)(n0 + row) * DM + k0 + c4 * 4);
        }
        asm volatile("cp.async.commit_group;" ::: "memory");
    };

    load(0, 0);
    load(1, 1);

    for (int c = 0; c < NCH; ++c) {
        if (c + 1 < NCH) asm volatile("cp.async.wait_group 1;" ::: "memory");
        else             asm volatile("cp.async.wait_group 0;" ::: "memory");
        __syncthreads();

        const float* as = As + (c & 1) * 128 * GPITCH;
        const float* bs = Bs + (c & 1) * 128 * GPITCH;
#pragma unroll
        for (int ks = 0; ks < 4; ks++) {
            const int kb = ks * 8;
            uint32_t a[4][4], b[4][2];
#pragma unroll
            for (int mt = 0; mt < 4; mt++) {
                int r = wm + mt * 16 + g;
                a[mt][0] = __float_as_uint(as[r * GPITCH + kb + t]);
                a[mt][1] = __float_as_uint(as[(r + 8) * GPITCH + kb + t]);
                a[mt][2] = __float_as_uint(as[r * GPITCH + kb + t + 4]);
                a[mt][3] = __float_as_uint(as[(r + 8) * GPITCH + kb + t + 4]);
            }
#pragma unroll
            for (int nt = 0; nt < 4; nt++) {
                int cn = wn + nt * 8 + g;
                b[nt][0] = __float_as_uint(bs[cn * GPITCH + kb + t]);
                b[nt][1] = __float_as_uint(bs[cn * GPITCH + kb + t + 4]);
            }
#pragma unroll
            for (int mt = 0; mt < 4; mt++)
#pragma unroll
                for (int nt = 0; nt < 4; nt++)
                    MMA8(acc[mt][nt], a[mt], b[nt]);
        }
        __syncthreads();
        if (c + 2 < NCH) load(c + 2, c & 1);
    }

    const int hh = blockIdx.x;
#pragma unroll
    for (int mt = 0; mt < 4; mt++) {
        int m = m0 + wm + mt * 16 + g;
        int bb = m >> 10, sp = m & 1023;
#pragma unroll
        for (int nt = 0; nt < 4; nt++) {
            int d = wn + nt * 8 + 2 * t;
            int n = n0 + d;
            float b0v = __ldg(bias + n), b1v = __ldg(bias + n + 1);
            float2 v0 = make_float2(acc[mt][nt][0] + b0v, acc[mt][nt][1] + b1v);
            float2 v1 = make_float2(acc[mt][nt][2] + b0v, acc[mt][nt][3] + b1v);
            if (mode) {
                float* dst = outp + (size_t)m * DM + n;
                *(float2*)dst            = v0;
                *(float2*)(dst + 8 * DM) = v1;
            } else if (z == 0) {
                v0.x = rna_tf32(v0.x); v0.y = rna_tf32(v0.y);
                v1.x = rna_tf32(v1.x); v1.y = rna_tf32(v1.y);
                float* dst = g_q + ((size_t)(bb * NH + hh) * S_NEW + sp) * DK + d;
                *(float2*)dst            = v0;
                *(float2*)(dst + 8 * DK) = v1;
            } else {
                float* dst = cache_out
                    + ((size_t)(((z - 1) * BB + bb) * NH + hh) * S_TOT
                       + S_CACHE + sp) * DK + d;
                *(float2*)dst            = v0;
                *(float2*)(dst + 8 * DK) = v1;
            }
        }
    }
}

// ---------------------------------------------------------------------------
// 3) Causal flash attention on tensor cores, pipelined:
//    - K tiles double-buffered via cp.async (next tile loads under S-MMA)
//    - V prefetched into registers in 2 halves, STS after each S-MMA half
// ---------------------------------------------------------------------------
#define FL_SMEM ((128*132 + 2*64*132 + 128*68 + 128*68) * 4)   // 204800 B

__global__ __launch_bounds__(256, 1)
void flash_mma_kernel(const float* __restrict__ cache_out) {
    extern __shared__ float smf[];
    float* Qs   = smf;                        // [128][132]
    float* Kbuf = Qs + 128 * 132;             // [2][64][132]
    float* Vt   = Kbuf + 2 * 64 * 132;        // [128][68]
    float* Ps   = Vt + 128 * 68;              // [128][68]

    const int qt = 7 - (int)blockIdx.x;       // longest tiles first
    const int h  = blockIdx.y;
    const int b  = blockIdx.z;
    const int q0 = qt << 7;
    const int tid  = threadIdx.x;
    const int warp = tid >> 5, lane = tid & 31;
    const int g = lane >> 2, t = lane & 3;
    const int wm = warp << 4;

    const float* Qg = g_q + ((size_t)(b * NH + h) * S_NEW + q0) * DK;
    const float* Kg = cache_out + (size_t)(b * NH + h) * S_TOT * DK;
    const float* Vg = cache_out + (size_t)((BB + b) * NH + h) * S_TOT * DK;

    const uint32_t sQ = smem_u32(Qs), sKb = smem_u32(Kbuf);

    auto loadK = [&](int kt) {
        const float* kp = Kg + (size_t)(kt * 64) * DK;
        const uint32_t dstb = sKb + (uint32_t)(kt & 1) * 64 * 132 * 4;
#pragma unroll
        for (int i = 0; i < 8; i++) {
            int idx = tid + i * 256;          // 0..2047
            int row = idx >> 5, c16 = idx & 31;
            cp16(dstb + (row * 132 + c16 * 4) * 4, kp + (size_t)row * DK + c16 * 4);
        }
        asm volatile("cp.async.commit_group;" ::: "memory");
    };

    // Q tile via cp.async (128x128)
#pragma unroll
    for (int i = 0; i < 16; i++) {
        int idx = tid + i * 256;
        int row = idx >> 5, c16 = idx & 31;
        cp16(sQ + (row * 132 + c16 * 4) * 4, Qg + (size_t)row * DK + c16 * 4);
    }
    asm volatile("cp.async.commit_group;" ::: "memory");
    loadK(0);

    float O[16][4];
    float M[2] = {-1e30f, -1e30f}, L[2] = {0.f, 0.f};
#pragma unroll
    for (int i = 0; i < 16; i++) { O[i][0] = O[i][1] = O[i][2] = O[i][3] = 0.f; }

    const float cs = 0.0883883476483184f * 1.4426950408889634f; // 1/sqrt(128)*log2e
    const int ntiles = 50 + 2 * qt;

    for (int kt = 0; kt < ntiles; ++kt) {
        asm volatile("cp.async.wait_group 0;" ::: "memory");   // K[kt] (+Q on kt=0)
        __syncthreads();               // prior PV done; Kbuf[(kt+1)&1] free
        if (kt + 1 < ntiles) loadK(kt + 1);   // overlaps with S-MMA below

        const float* Ksb = Kbuf + (kt & 1) * 64 * 132;
        const float* vp  = Vg + (size_t)(kt * 64) * DK;

        float s[8][4];
#pragma unroll
        for (int nt = 0; nt < 8; nt++) { s[nt][0] = s[nt][1] = s[nt][2] = s[nt][3] = 0.f; }

        // ---- V prefetch half A (j 0..31) ----
        float4 va[4];
#pragma unroll
        for (int i = 0; i < 4; i++) {
            int idx = tid + i * 256;
            int d = idx & 127, j0 = (idx >> 7) << 2;
            va[i].x = vp[(size_t)(j0 + 0) * DK + d];
            va[i].y = vp[(size_t)(j0 + 1) * DK + d];
            va[i].z = vp[(size_t)(j0 + 2) * DK + d];
            va[i].w = vp[(size_t)(j0 + 3) * DK + d];
        }

        // ---- S-MMA ks 0..7 (V half-A latency hides here) ----
#pragma unroll
        for (int ks = 0; ks < 8; ks++) {
            const int kb = ks * 8;
            uint32_t a[4];
            a[0] = __float_as_uint(Qs[(wm + g) * 132 + kb + t]);
            a[1] = __float_as_uint(Qs[(wm + g + 8) * 132 + kb + t]);
            a[2] = __float_as_uint(Qs[(wm + g) * 132 + kb + t + 4]);
            a[3] = __float_as_uint(Qs[(wm + g + 8) * 132 + kb + t + 4]);
#pragma unroll
            for (int nt = 0; nt < 8; nt++) {
                uint32_t bf[2];
                bf[0] = __float_as_uint(Ksb[(nt * 8 + g) * 132 + kb + t]);
                bf[1] = __float_as_uint(Ksb[(nt * 8 + g) * 132 + kb + t + 4]);
                MMA8(s[nt], a, bf);
            }
        }

        // ---- STS V half A; prefetch half B (j 32..63) ----
#pragma unroll
        for (int i = 0; i < 4; i++) {
            int idx = tid + i * 256;
            int d = idx & 127, j0 = (idx >> 7) << 2;
            *(float4*)(Vt + d * 68 + j0) = va[i];
        }
#pragma unroll
        for (int i = 0; i < 4; i++) {
            int idx = tid + (i + 4) * 256;
            int d = idx & 127, j0 = (idx >> 7) << 2;
            va[i].x = vp[(size_t)(j0 + 0) * DK + d];
            va[i].y = vp[(size_t)(j0 + 1) * DK + d];
            va[i].z = vp[(size_t)(j0 + 2) * DK + d];
            va[i].w = vp[(size_t)(j0 + 3) * DK + d];
        }

        // ---- S-MMA ks 8..15 ----
#pragma unroll
        for (int ks = 8; ks < 16; ks++) {
            const int kb = ks * 8;
            uint32_t a[4];
            a[0] = __float_as_uint(Qs[(wm + g) * 132 + kb + t]);
            a[1] = __float_as_uint(Qs[(wm + g + 8) * 132 + kb + t]);
            a[2] = __float_as_uint(Qs[(wm + g) * 132 + kb + t + 4]);
            a[3] = __float_as_uint(Qs[(wm + g + 8) * 132 + kb + t + 4]);
#pragma unroll
            for (int nt = 0; nt < 8; nt++) {
                uint32_t bf[2];
                bf[0] = __float_as_uint(Ksb[(nt * 8 + g) * 132 + kb + t]);
                bf[1] = __float_as_uint(Ksb[(nt * 8 + g) * 132 + kb + t + 4]);
                MMA8(s[nt], a, bf);
            }
        }

        // ---- STS V half B ----
#pragma unroll
        for (int i = 0; i < 4; i++) {
            int idx = tid + (i + 4) * 256;
            int d = idx & 127, j0 = (idx >> 7) << 2;
            *(float4*)(Vt + d * 68 + j0) = va[i];
        }

        // ---- online softmax ----
        const bool domask = (kt * 64 + 63 >= S_CACHE + q0);
#pragma unroll
        for (int r = 0; r < 2; r++) {
            const int ml = wm + g + 8 * r;
            float mx = -1e30f;
#pragma unroll
            for (int nt = 0; nt < 8; nt++) {
                float v0 = s[nt][2 * r]     * cs;
                float v1 = s[nt][2 * r + 1] * cs;
                if (domask) {
                    int j = kt * 64 + nt * 8 + 2 * t;
                    if (j     >= S_CACHE + q0 + ml) v0 = -1e30f;
                    if (j + 1 >= S_CACHE + q0 + ml) v1 = -1e30f;
                }
                s[nt][2 * r] = v0; s[nt][2 * r + 1] = v1;
                mx = fmaxf(mx, fmaxf(v0, v1));
            }
            mx = fmaxf(mx, __shfl_xor_sync(0xffffffffu, mx, 1));
            mx = fmaxf(mx, __shfl_xor_sync(0xffffffffu, mx, 2));
            float newM  = fmaxf(M[r], mx);
            float alpha = exp2f(M[r] - newM);
            M[r] = newM;
            float rs = 0.f;
#pragma unroll
            for (int nt = 0; nt < 8; nt++) {
                float p0 = rna_tf32(exp2f(s[nt][2 * r]     - newM));
                float p1 = rna_tf32(exp2f(s[nt][2 * r + 1] - newM));
                rs += p0 + p1;
                *(float2*)(Ps + ml * 68 + nt * 8 + 2 * t) = make_float2(p0, p1);
            }
            rs += __shfl_xor_sync(0xffffffffu, rs, 1);
            rs += __shfl_xor_sync(0xffffffffu, rs, 2);
            L[r] = L[r] * alpha + rs;
#pragma unroll
            for (int dt = 0; dt < 16; dt++) {
                O[dt][2 * r]     *= alpha;
                O[dt][2 * r + 1] *= alpha;
            }
        }
        __syncthreads();               // Vt (all threads) visible for PV

        // ---- O += P @ V (warp: 16x128, k=64) ----
#pragma unroll
        for (int jb = 0; jb < 8; jb++) {
            const int kb = jb * 8;
            uint32_t a[4];
            a[0] = __float_as_uint(Ps[(wm + g) * 68 + kb + t]);
            a[1] = __float_as_uint(Ps[(wm + g + 8) * 68 + kb + t]);
            a[2] = __float_as_uint(Ps[(wm + g) * 68 + kb + t + 4]);
            a[3] = __float_as_uint(Ps[(wm + g + 8) * 68 + kb + t + 4]);
#pragma unroll
            for (int dt = 0; dt < 16; dt++) {
                uint32_t bf[2];
                bf[0] = __float_as_uint(Vt[(dt * 8 + g) * 68 + kb + t]);
                bf[1] = __float_as_uint(Vt[(dt * 8 + g) * 68 + kb + t + 4]);
                MMA8(O[dt], a, bf);
            }
        }
    }

    // epilogue: normalize + RNA-round + write g_att [b,s,h*dk]
#pragma unroll
    for (int r = 0; r < 2; r++) {
        float inv = 1.f / L[r];
        int m = q0 + wm + g + 8 * r;
        float* dst = g_att + (size_t)(b * S_NEW + m) * DM + h * DK;
#pragma unroll
        for (int dt = 0; dt < 16; dt++) {
            float2 v = make_float2(rna_tf32(O[dt][2 * r] * inv),
                                   rna_tf32(O[dt][2 * r + 1] * inv));
            *(float2*)(dst + dt * 8 + 2 * t) = v;
        }
    }
}

// ---------------------------------------------------------------------------
// Launch
// ---------------------------------------------------------------------------
extern "C" void kernel_launch(void* const* d_in, const int* in_sizes, int n_in,
                              void* d_out, int out_size) {
    const float* x     = (const float*)d_in[0];
    const float* cache = (const float*)d_in[1];
    const float* Wq    = (const float*)d_in[2];
    const float* bq    = (const float*)d_in[3];
    const float* Wk    = (const float*)d_in[4];
    const float* bk    = (const float*)d_in[5];
    const float* Wv    = (const float*)d_in[6];
    const float* bv    = (const float*)d_in[7];
    const float* Wo    = (const float*)d_in[8];
    const float* bo    = (const float*)d_in[9];

    float* out       = (float*)d_out;
    float* cache_out = out + (size_t)BB * S_NEW * DM;

    // 0) round x + weights to tf32 (RNA)
    round_kernel<<<4096, 256>>>(x, Wq, Wk, Wv, Wo);

    // 1) copy old cache rows
    {
        int total  = 2 * BB * NH * (S_CACHE * DK / 4);
        int blocks = (total + 255) / 256;
        copy_cache_kernel<<<blocks, 256>>>((const float4*)cache, (float4*)cache_out);
    }

    // 2) fused QKV projections on tensor cores (z=0 Q, z=1 K, z=2 V)
    cudaFuncSetAttribute(gemm_mma_kernel,
                         cudaFuncAttributeMaxDynamicSharedMemorySize, GM_SMEM);
    gemm_mma_kernel<<<dim3(16, 16, 3), 256, GM_SMEM>>>(bq, bk, bv,
                                                       cache_out, nullptr, 0);

    // 3) flash attention on tensor cores (pipelined)
    cudaFuncSetAttribute(flash_mma_kernel,
                         cudaFuncAttributeMaxDynamicSharedMemorySize, FL_SMEM);
    flash_mma_kernel<<<dim3(8, NH, BB), 256, FL_SMEM>>>(cache_out);

    // 4) output projection on tensor cores
    gemm_mma_kernel<<<dim3(16, 16, 1), 256, GM_SMEM>>>(bo, nullptr, nullptr,
                                                       nullptr, out, 1);
}

// round 15
// speedup vs baseline: 1.1390x; 1.0447x over previous
#include <cuda_runtime.h>
#include <cstdint>

// Problem constants
#define BB      2
#define S_NEW   1024
#define S_CACHE 3072
#define S_TOT   4096
#define NH      16
#define DK      128
#define DM      2048

// Scratch (device globals — no allocation allowed)
__device__ float g_q[BB*NH*S_NEW*DK];    // Q in [b,h,s,d] (tf32-rounded)
__device__ float g_att[BB*S_NEW*DM];     // attention output [b,s,h*dk] (tf32-rounded)
__device__ float g_xr[BB*S_NEW*DM];      // x rounded to tf32
__device__ float g_wr[4*DM*DM];          // Wq,Wk,Wv,Wo rounded to tf32

// ---------------------------------------------------------------------------
// helpers
// ---------------------------------------------------------------------------
__device__ __forceinline__ uint32_t smem_u32(const void* p) {
    uint32_t a;
    asm("{ .reg .u64 t; cvta.to.shared.u64 t, %1; cvt.u32.u64 %0, t; }"
        : "=r"(a) : "l"(p));
    return a;
}
__device__ __forceinline__ void cp16(uint32_t so, const void* gp) {
    asm volatile("cp.async.cg.shared.global [%0], [%1], 16;" :: "r"(so), "l"(gp));
}
__device__ __forceinline__ float rna_tf32(float x) {
    uint32_t u;
    asm("cvt.rna.tf32.f32 %0, %1;" : "=r"(u) : "f"(x));
    return __uint_as_float(u);
}

// D(16x8) += A(16x8,row) * B(8x8,col)  — tf32 tensor-core MMA (baseline PTX)
#define MMA8(c, a, b)                                                          \
    asm volatile("mma.sync.aligned.m16n8k8.row.col.f32.tf32.tf32.f32 "        \
        "{%0,%1,%2,%3}, {%4,%5,%6,%7}, {%8,%9}, {%0,%1,%2,%3};"               \
        : "+f"((c)[0]), "+f"((c)[1]), "+f"((c)[2]), "+f"((c)[3])              \
        : "r"((a)[0]), "r"((a)[1]), "r"((a)[2]), "r"((a)[3]),                 \
          "r"((b)[0]), "r"((b)[1]))

// ---------------------------------------------------------------------------
// 0) Round x and the four weight matrices to tf32 (RNA, unbiased) once.
// ---------------------------------------------------------------------------
__global__ void round_kernel(const float* __restrict__ x,
                             const float* __restrict__ Wq,
                             const float* __restrict__ Wk,
                             const float* __restrict__ Wv,
                             const float* __restrict__ Wo) {
    const int SEG = DM * DM;
    int i = blockIdx.x * blockDim.x + threadIdx.x;
    const int stride = gridDim.x * blockDim.x;
    for (; i < 5 * SEG; i += stride) {
        int seg = i >> 22, o = i & (SEG - 1);
        float v;
        float* dst;
        if (seg == 0)      { v = x[o];  dst = g_xr + o; }
        else               { const float* W = (seg == 1) ? Wq : (seg == 2) ? Wk
                                              : (seg == 3) ? Wv : Wo;
                             v = W[o]; dst = g_wr + (size_t)(seg - 1) * SEG + o; }
        *dst = rna_tf32(v);
    }
}

// ---------------------------------------------------------------------------
// 1) Copy old cache rows into the updated-cache output region
// ---------------------------------------------------------------------------
__global__ void copy_cache_kernel(const float4* __restrict__ src,
                                  float4* __restrict__ dst) {
    int i = blockIdx.x * blockDim.x + threadIdx.x;
    const int per   = S_CACHE * DK / 4;
    const int total = 2 * BB * NH * per;
    if (i < total) {
        int c = i / per;
        int w = i - c * per;
        dst[(size_t)c * (S_TOT * DK / 4) + w] = src[i];
    }
}

// ---------------------------------------------------------------------------
// 2/4) Tensor-core GEMM (mma.sync tf32): Y[M,N] = A[M,K] @ W[N,K]^T + bias.
//      (unchanged from R13 passing version)
// ---------------------------------------------------------------------------
#define KC      32
#define GPITCH  36
#define NCH     (DM / KC)
#define GM_SMEM (2 * 2 * 128 * GPITCH * 4)

__global__ __launch_bounds__(256, 2)
void gemm_mma_kernel(const float* __restrict__ B0,
                     const float* __restrict__ B1,
                     const float* __restrict__ B2,
                     float* __restrict__ cache_out,
                     float* __restrict__ outp,
                     int mode) {
    extern __shared__ float gsm[];
    float* As = gsm;
    float* Bs = gsm + 2 * 128 * GPITCH;

    const int tid = threadIdx.x;
    const int warp = tid >> 5, lane = tid & 31;
    const int g = lane >> 2, t = lane & 3;
    const int z = blockIdx.z;

    const float* Ap = mode ? g_att : g_xr;
    const float* W  = g_wr + (size_t)(mode ? 3 : z) * DM * DM;
    const float* bias = mode ? B0 : (z == 0 ? B0 : (z == 1 ? B1 : B2));

    const int m0 = blockIdx.y * 128, n0 = blockIdx.x * 128;
    const int wm = (warp & 1) * 64, wn = (warp >> 1) * 32;

    const uint32_t sA = smem_u32(As);
    const uint32_t sB = smem_u32(Bs);

    float acc[4][4][4];
#pragma unroll
    for (int mt = 0; mt < 4; mt++)
#pragma unroll
        for (int nt = 0; nt < 4; nt++)
#pragma unroll
            for (int r = 0; r < 4; r++) acc[mt][nt][r] = 0.f;

    auto load = [&](int c, int buf) {
        const int k0 = c * KC;
        const uint32_t offA = sA + (uint32_t)buf * 128 * GPITCH * 4;
        const uint32_t offB = sB + (uint32_t)buf * 128 * GPITCH * 4;
#pragma unroll
        for (int i = 0; i < 4; i++) {
            int idx = tid + i * 256;
            int row = idx >> 3, c4 = idx & 7;
            cp16(offA + (row * GPITCH + c4 * 4) * 4,
                 Ap + (size_t)(m0 + row) * DM + k0 + c4 * 4);
            cp16(offB + (row * GPITCH + c4 * 4) * 4,
                 W + (size_t)(n0 + row) * DM + k0 + c4 * 4);
        }
        asm volatile("cp.async.commit_group;" ::: "memory");
    };

    load(0, 0);
    load(1, 1);

    for (int c = 0; c < NCH; ++c) {
        if (c + 1 < NCH) asm volatile("cp.async.wait_group 1;" ::: "memory");
        else             asm volatile("cp.async.wait_group 0;" ::: "memory");
        __syncthreads();

        const float* as = As + (c & 1) * 128 * GPITCH;
        const float* bs = Bs + (c & 1) * 128 * GPITCH;
#pragma unroll
        for (int ks = 0; ks < 4; ks++) {
            const int kb = ks * 8;
            uint32_t a[4][4], b[4][2];
#pragma unroll
            for (int mt = 0; mt < 4; mt++) {
                int r = wm + mt * 16 + g;
                a[mt][0] = __float_as_uint(as[r * GPITCH + kb + t]);
                a[mt][1] = __float_as_uint(as[(r + 8) * GPITCH + kb + t]);
                a[mt][2] = __float_as_uint(as[r * GPITCH + kb + t + 4]);
                a[mt][3] = __float_as_uint(as[(r + 8) * GPITCH + kb + t + 4]);
            }
#pragma unroll
            for (int nt = 0; nt < 4; nt++) {
                int cn = wn + nt * 8 + g;
                b[nt][0] = __float_as_uint(bs[cn * GPITCH + kb + t]);
                b[nt][1] = __float_as_uint(bs[cn * GPITCH + kb + t + 4]);
            }
#pragma unroll
            for (int mt = 0; mt < 4; mt++)
#pragma unroll
                for (int nt = 0; nt < 4; nt++)
                    MMA8(acc[mt][nt], a[mt], b[nt]);
        }
        __syncthreads();
        if (c + 2 < NCH) load(c + 2, c & 1);
    }

    const int hh = blockIdx.x;
#pragma unroll
    for (int mt = 0; mt < 4; mt++) {
        int m = m0 + wm + mt * 16 + g;
        int bb = m >> 10, sp = m & 1023;
#pragma unroll
        for (int nt = 0; nt < 4; nt++) {
            int d = wn + nt * 8 + 2 * t;
            int n = n0 + d;
            float b0v = __ldg(bias + n), b1v = __ldg(bias + n + 1);
            float2 v0 = make_float2(acc[mt][nt][0] + b0v, acc[mt][nt][1] + b1v);
            float2 v1 = make_float2(acc[mt][nt][2] + b0v, acc[mt][nt][3] + b1v);
            if (mode) {
                float* dst = outp + (size_t)m * DM + n;
                *(float2*)dst            = v0;
                *(float2*)(dst + 8 * DM) = v1;
            } else if (z == 0) {
                v0.x = rna_tf32(v0.x); v0.y = rna_tf32(v0.y);
                v1.x = rna_tf32(v1.x); v1.y = rna_tf32(v1.y);
                float* dst = g_q + ((size_t)(bb * NH + hh) * S_NEW + sp) * DK + d;
                *(float2*)dst            = v0;
                *(float2*)(dst + 8 * DK) = v1;
            } else {
                float* dst = cache_out
                    + ((size_t)(((z - 1) * BB + bb) * NH + hh) * S_TOT
                       + S_CACHE + sp) * DK + d;
                *(float2*)dst            = v0;
                *(float2*)(dst + 8 * DK) = v1;
            }
        }
    }
}

// ---------------------------------------------------------------------------
// 3) Causal flash attention, BQ=256, warp tile m32 (b-fragments reused 2x),
//    Q fragment-ordered in smem, K natural double-buffered via cp.async,
//    V fragment-ordered (stride-66 tiles), P -> A-fragments via shuffles.
// ---------------------------------------------------------------------------
// smem floats: Qf 16*16*32*4 = 32768 | Kb 2*64*132 = 16896 | Vf 8*16*66 = 8448
#define FL_SMEM ((32768 + 16896 + 8448) * 4)   // 232448 B (== max dynamic)

__global__ __launch_bounds__(256)
void flash_mma_kernel(const float* __restrict__ cache_out) {
    extern __shared__ float smf[];
    float* Qf = smf;                    // [ks16][sub16][lane32][4]
    float* Kb = Qf + 32768;             // [2][64*132] natural
    float* Vf = Kb + 16896;             // [jb8][dt16] tiles of 66 floats

    const int qt = 3 - (int)blockIdx.x;
    const int h  = blockIdx.y;
    const int b  = blockIdx.z;
    const int q0 = qt << 8;
    const int tid  = threadIdx.x;
    const int warp = tid >> 5, lane = tid & 31;
    const int g = lane >> 2, t = lane & 3;
    const int base = warp << 5;              // this warp's 32 query rows
    const int subA = warp * 2, subB = warp * 2 + 1;

    const float* Qg = g_q + ((size_t)(b * NH + h) * S_NEW + q0) * DK;
    const float* Kg = cache_out + (size_t)(b * NH + h) * S_TOT * DK;
    const float* Vg = cache_out + (size_t)((BB + b) * NH + h) * S_TOT * DK;

    const uint32_t sKb = smem_u32(Kb);

    auto loadK = [&](int kt) {
        const float* kp = Kg + (size_t)(kt * 64) * DK;
        const uint32_t dstb = sKb + (uint32_t)(kt & 1) * 64 * 132 * 4;
#pragma unroll
        for (int i = 0; i < 8; i++) {
            int idx = tid + i * 256;
            int row = idx >> 5, c16 = (idx & 31) << 2;
            cp16(dstb + (row * 132 + c16) * 4, kp + (size_t)row * DK + c16);
        }
        asm volatile("cp.async.commit_group;" ::: "memory");
    };

    loadK(0);

    // Stage Q in A-fragment order (once per CTA; bank conflicts amortized)
#pragma unroll
    for (int i = 0; i < 32; i++) {
        int idx = tid + i * 256;            // 0..8191
        int row = idx >> 5, c4 = (idx & 31) << 2;
        float4 v = *(const float4*)(Qg + (size_t)row * DK + c4);
        int ks   = c4 >> 3;
        int comp = ((row >> 3) & 1) | ((c4 & 4) >> 1);
        int sub  = row >> 4;
        float* dst = Qf + (((ks * 16 + sub) * 32 + ((row & 7) << 2)) << 2) + comp;
        dst[0] = v.x; dst[4] = v.y; dst[8] = v.z; dst[12] = v.w;
    }

    float O[2][16][4];
    float M[4] = {-1e30f, -1e30f, -1e30f, -1e30f};
    float L[4] = {0.f, 0.f, 0.f, 0.f};
#pragma unroll
    for (int s2 = 0; s2 < 2; s2++)
#pragma unroll
        for (int dt = 0; dt < 16; dt++)
#pragma unroll
            for (int r = 0; r < 4; r++) O[s2][dt][r] = 0.f;

    const float cs = 0.0883883476483184f * 1.4426950408889634f; // 1/sqrt(128)*log2e
    const int ntiles = 52 + 4 * qt;

    const int slA = (lane & 28) | (t >> 1);
    const int slB = slA + 2;
    const bool odd = (t & 1);

    for (int kt = 0; kt < ntiles; ++kt) {
        asm volatile("cp.async.wait_group 0;" ::: "memory");   // K[kt] landed
        __syncthreads();            // prior tile fully consumed everywhere
        if (kt + 1 < ntiles) loadK(kt + 1);    // runs under S-MMA

        const float* Ksb = Kb + (kt & 1) * 64 * 132;
        const float* vp  = Vg + (size_t)(kt * 64) * DK;

        float s[2][8][4];
#pragma unroll
        for (int s2 = 0; s2 < 2; s2++)
#pragma unroll
            for (int nt = 0; nt < 8; nt++)
#pragma unroll
                for (int r = 0; r < 4; r++) s[s2][nt][r] = 0.f;

        // S = Q K^T in 4 quarters; V tile staged (LDG->frag STS) between them
#pragma unroll
        for (int qtr = 0; qtr < 4; ++qtr) {
            float4 vr0, vr1;
            {
                int idx = tid + (qtr * 2) * 256;           // 0..2047
                vr0 = *(const float4*)(vp + (size_t)(idx >> 5) * DK + ((idx & 31) << 2));
                idx += 256;
                vr1 = *(const float4*)(vp + (size_t)(idx >> 5) * DK + ((idx & 31) << 2));
            }
#pragma unroll
            for (int ks = qtr * 4; ks < qtr * 4 + 4; ++ks) {
                float4 aA = *(const float4*)(Qf + (((ks * 16 + subA) * 32 + lane) << 2));
                float4 aB = *(const float4*)(Qf + (((ks * 16 + subB) * 32 + lane) << 2));
                const uint32_t* aAu = reinterpret_cast<const uint32_t*>(&aA);
                const uint32_t* aBu = reinterpret_cast<const uint32_t*>(&aB);
#pragma unroll
                for (int nt = 0; nt < 8; nt++) {
                    uint32_t bf[2];
                    bf[0] = __float_as_uint(Ksb[(nt * 8 + g) * 132 + ks * 8 + t]);
                    bf[1] = __float_as_uint(Ksb[(nt * 8 + g) * 132 + ks * 8 + t + 4]);
                    MMA8(s[0][nt], aAu, bf);
                    MMA8(s[1][nt], aBu, bf);
                }
            }
            // store the V chunk in B-fragment order (tile stride 66)
#pragma unroll
            for (int j = 0; j < 2; j++) {
                int idx = tid + (qtr * 2 + j) * 256;
                int jr = idx >> 5, d0 = (idx & 31) << 2;
                int jb = jr >> 3, tj = jr & 3, compV = (jr >> 2) & 1;
                int dt = d0 >> 3;
                float4 vv = j ? vr1 : vr0;
                float* dv = Vf + (jb * 16 + dt) * 66
                          + ((((d0 & 7) << 2) + tj) << 1) + compV;
                dv[0] = vv.x; dv[8] = vv.y; dv[16] = vv.z; dv[24] = vv.w;
            }
        }

        // ---- online softmax (4 row groups per thread) ----
        const bool domask = (kt * 64 + 63 >= S_CACHE + q0 + base);
#pragma unroll
        for (int sub = 0; sub < 2; sub++)
#pragma unroll
        for (int r = 0; r < 2; r++) {
            const int grp = sub * 2 + r;
            const int rowg = q0 + base + sub * 16 + g + 8 * r;  // global q row
            float mx = -1e30f;
#pragma unroll
            for (int nt = 0; nt < 8; nt++) {
                float v0 = s[sub][nt][2 * r]     * cs;
                float v1 = s[sub][nt][2 * r + 1] * cs;
                if (domask) {
                    int j = kt * 64 + nt * 8 + 2 * t;
                    if (j     >= S_CACHE + rowg) v0 = -1e30f;
                    if (j + 1 >= S_CACHE + rowg) v1 = -1e30f;
                }
                s[sub][nt][2 * r] = v0; s[sub][nt][2 * r + 1] = v1;
                mx = fmaxf(mx, fmaxf(v0, v1));
            }
            mx = fmaxf(mx, __shfl_xor_sync(0xffffffffu, mx, 1));
            mx = fmaxf(mx, __shfl_xor_sync(0xffffffffu, mx, 2));
            float newM  = fmaxf(M[grp], mx);
            float alpha = exp2f(M[grp] - newM);
            M[grp] = newM;
            float rs = 0.f;
#pragma unroll
            for (int nt = 0; nt < 8; nt++) {
                float p0 = rna_tf32(exp2f(s[sub][nt][2 * r]     - newM));
                float p1 = rna_tf32(exp2f(s[sub][nt][2 * r + 1] - newM));
                rs += p0 + p1;
                s[sub][nt][2 * r] = p0; s[sub][nt][2 * r + 1] = p1;
            }
            rs += __shfl_xor_sync(0xffffffffu, rs, 1);
            rs += __shfl_xor_sync(0xffffffffu, rs, 2);
            L[grp] = L[grp] * alpha + rs;
#pragma unroll
            for (int dt = 0; dt < 16; dt++) {
                O[sub][dt][2 * r]     *= alpha;
                O[sub][dt][2 * r + 1] *= alpha;
            }
        }
        __syncthreads();            // Vf fully written, visible to all warps

        // ---- O += P @ V : P-fragments from registers via shuffles ----
#pragma unroll
        for (int jb = 0; jb < 8; jb++) {
            uint32_t aF[2][4];
#pragma unroll
            for (int sub = 0; sub < 2; sub++) {
                float p00 = __shfl_sync(0xffffffffu, s[sub][jb][0], slA);
                float p01 = __shfl_sync(0xffffffffu, s[sub][jb][1], slA);
                float p02 = __shfl_sync(0xffffffffu, s[sub][jb][0], slB);
                float p03 = __shfl_sync(0xffffffffu, s[sub][jb][1], slB);
                float p10 = __shfl_sync(0xffffffffu, s[sub][jb][2], slA);
                float p11 = __shfl_sync(0xffffffffu, s[sub][jb][3], slA);
                float p12 = __shfl_sync(0xffffffffu, s[sub][jb][2], slB);
                float p13 = __shfl_sync(0xffffffffu, s[sub][jb][3], slB);
                aF[sub][0] = __float_as_uint(odd ? p01 : p00);
                aF[sub][1] = __float_as_uint(odd ? p11 : p10);
                aF[sub][2] = __float_as_uint(odd ? p03 : p02);
                aF[sub][3] = __float_as_uint(odd ? p13 : p12);
            }
#pragma unroll
            for (int dt = 0; dt < 16; dt++) {
                const float2 bv = *(const float2*)(Vf + (jb * 16 + dt) * 66 + (lane << 1));
                uint32_t bf[2];
                bf[0] = __float_as_uint(bv.x);
                bf[1] = __float_as_uint(bv.y);
                MMA8(O[0][dt], aF[0], bf);
                MMA8(O[1][dt], aF[1], bf);
            }
        }
    }

    // epilogue: normalize + RNA-round + write g_att [b,s,h*dk]
#pragma unroll
    for (int sub = 0; sub < 2; sub++)
#pragma unroll
    for (int r = 0; r < 2; r++) {
        const int grp = sub * 2 + r;
        float inv = 1.f / L[grp];
        int rowg = q0 + base + sub * 16 + g + 8 * r;
        float* dst = g_att + (size_t)(b * S_NEW + rowg) * DM + h * DK;
#pragma unroll
        for (int dt = 0; dt < 16; dt++) {
            float2 v = make_float2(rna_tf32(O[sub][dt][2 * r] * inv),
                                   rna_tf32(O[sub][dt][2 * r + 1] * inv));
            *(float2*)(dst + dt * 8 + 2 * t) = v;
        }
    }
}

// ---------------------------------------------------------------------------
// Launch
// ---------------------------------------------------------------------------
extern "C" void kernel_launch(void* const* d_in, const int* in_sizes, int n_in,
                              void* d_out, int out_size) {
    const float* x     = (const float*)d_in[0];
    const float* cache = (const float*)d_in[1];
    const float* Wq    = (const float*)d_in[2];
    const float* bq    = (const float*)d_in[3];
    const float* Wk    = (const float*)d_in[4];
    const float* bk    = (const float*)d_in[5];
    const float* Wv    = (const float*)d_in[6];
    const float* bv    = (const float*)d_in[7];
    const float* Wo    = (const float*)d_in[8];
    const float* bo    = (const float*)d_in[9];

    float* out       = (float*)d_out;
    float* cache_out = out + (size_t)BB * S_NEW * DM;

    // 0) round x + weights to tf32 (RNA)
    round_kernel<<<4096, 256>>>(x, Wq, Wk, Wv, Wo);

    // 1) copy old cache rows
    {
        int total  = 2 * BB * NH * (S_CACHE * DK / 4);
        int blocks = (total + 255) / 256;
        copy_cache_kernel<<<blocks, 256>>>((const float4*)cache, (float4*)cache_out);
    }

    // 2) fused QKV projections on tensor cores (z=0 Q, z=1 K, z=2 V)
    cudaFuncSetAttribute(gemm_mma_kernel,
                         cudaFuncAttributeMaxDynamicSharedMemorySize, GM_SMEM);
    gemm_mma_kernel<<<dim3(16, 16, 3), 256, GM_SMEM>>>(bq, bk, bv,
                                                       cache_out, nullptr, 0);

    // 3) flash attention on tensor cores (BQ=256, m32 warp tiles)
    cudaFuncSetAttribute(flash_mma_kernel,
                         cudaFuncAttributeMaxDynamicSharedMemorySize, FL_SMEM);
    flash_mma_kernel<<<dim3(4, NH, BB), 256, FL_SMEM>>>(cache_out);

    // 4) output projection on tensor cores
    gemm_mma_kernel<<<dim3(16, 16, 1), 256, GM_SMEM>>>(bo, nullptr, nullptr,
                                                       nullptr, out, 1);
}

// round 16
// speedup vs baseline: 1.1800x; 1.0359x over previous
#include <cuda_runtime.h>
#include <cstdint>

// Problem constants
#define BB      2
#define S_NEW   1024
#define S_CACHE 3072
#define S_TOT   4096
#define NH      16
#define DK      128
#define DM      2048

// Scratch (device globals — no allocation allowed)
__device__ float g_q[BB*NH*S_NEW*DK];    // Q in [b,h,s,d] (tf32-rounded)
__device__ float g_att[BB*S_NEW*DM];     // attention output [b,s,h*dk] (tf32-rounded)
__device__ float g_xr[BB*S_NEW*DM];      // x rounded to tf32
__device__ float g_wr[4*DM*DM];          // Wq,Wk,Wv,Wo rounded to tf32

// ---------------------------------------------------------------------------
// helpers
// ---------------------------------------------------------------------------
__device__ __forceinline__ uint32_t smem_u32(const void* p) {
    uint32_t a;
    asm("{ .reg .u64 t; cvta.to.shared.u64 t, %1; cvt.u32.u64 %0, t; }"
        : "=r"(a) : "l"(p));
    return a;
}
__device__ __forceinline__ void cp16(uint32_t so, const void* gp) {
    asm volatile("cp.async.cg.shared.global [%0], [%1], 16;" :: "r"(so), "l"(gp));
}
__device__ __forceinline__ float rna_tf32(float x) {
    uint32_t u;
    asm("cvt.rna.tf32.f32 %0, %1;" : "=r"(u) : "f"(x));
    return __uint_as_float(u);
}

// D(16x8) += A(16x8,row) * B(8x8,col)  — tf32 tensor-core MMA (baseline PTX)
#define MMA8(c, a, b)                                                          \
    asm volatile("mma.sync.aligned.m16n8k8.row.col.f32.tf32.tf32.f32 "        \
        "{%0,%1,%2,%3}, {%4,%5,%6,%7}, {%8,%9}, {%0,%1,%2,%3};"               \
        : "+f"((c)[0]), "+f"((c)[1]), "+f"((c)[2]), "+f"((c)[3])              \
        : "r"((a)[0]), "r"((a)[1]), "r"((a)[2]), "r"((a)[3]),                 \
          "r"((b)[0]), "r"((b)[1]))

// ldmatrix.x4: 4x (8 rows x 16B). For tf32 data, thread T of matrix m gets
// element M[T>>2][T&3] (32-bit) — exactly the mma.m16n8k8 fragment layout.
#define LDSM4(r0, r1, r2, r3, addr)                                           \
    asm volatile("ldmatrix.sync.aligned.m8n8.x4.shared.b16 {%0,%1,%2,%3}, [%4];" \
        : "=r"(r0), "=r"(r1), "=r"(r2), "=r"(r3) : "r"(addr))

// ---------------------------------------------------------------------------
// 0) Round x and the four weight matrices to tf32 (RNA, unbiased) once.
// ---------------------------------------------------------------------------
__global__ void round_kernel(const float* __restrict__ x,
                             const float* __restrict__ Wq,
                             const float* __restrict__ Wk,
                             const float* __restrict__ Wv,
                             const float* __restrict__ Wo) {
    const int SEG = DM * DM;
    int i = blockIdx.x * blockDim.x + threadIdx.x;
    const int stride = gridDim.x * blockDim.x;
    for (; i < 5 * SEG; i += stride) {
        int seg = i >> 22, o = i & (SEG - 1);
        float v;
        float* dst;
        if (seg == 0)      { v = x[o];  dst = g_xr + o; }
        else               { const float* W = (seg == 1) ? Wq : (seg == 2) ? Wk
                                              : (seg == 3) ? Wv : Wo;
                             v = W[o]; dst = g_wr + (size_t)(seg - 1) * SEG + o; }
        *dst = rna_tf32(v);
    }
}

// ---------------------------------------------------------------------------
// 1) Copy old cache rows into the updated-cache output region
// ---------------------------------------------------------------------------
__global__ void copy_cache_kernel(const float4* __restrict__ src,
                                  float4* __restrict__ dst) {
    int i = blockIdx.x * blockDim.x + threadIdx.x;
    const int per   = S_CACHE * DK / 4;
    const int total = 2 * BB * NH * per;
    if (i < total) {
        int c = i / per;
        int w = i - c * per;
        dst[(size_t)c * (S_TOT * DK / 4) + w] = src[i];
    }
}

// ---------------------------------------------------------------------------
// 2/4) Tensor-core GEMM (mma.sync tf32): Y[M,N] = A[M,K] @ W[N,K]^T + bias.
//      128x128 tile, 8 warps (2Mx4N), KC=32, double-buffered cp.async,
//      fragments via ldmatrix.x4.
// ---------------------------------------------------------------------------
#define KC      32
#define GPITCH  36
#define NCH     (DM / KC)
#define GM_SMEM (2 * 2 * 128 * GPITCH * 4)

__global__ __launch_bounds__(256, 2)
void gemm_mma_kernel(const float* __restrict__ B0,
                     const float* __restrict__ B1,
                     const float* __restrict__ B2,
                     float* __restrict__ cache_out,
                     float* __restrict__ outp,
                     int mode) {
    extern __shared__ float gsm[];
    float* As = gsm;
    float* Bs = gsm + 2 * 128 * GPITCH;

    const int tid = threadIdx.x;
    const int warp = tid >> 5, lane = tid & 31;
    const int g = lane >> 2, t = lane & 3;
    const int mi = lane >> 3, rr = lane & 7;
    const int z = blockIdx.z;

    const float* Ap = mode ? g_att : g_xr;
    const float* W  = g_wr + (size_t)(mode ? 3 : z) * DM * DM;
    const float* bias = mode ? B0 : (z == 0 ? B0 : (z == 1 ? B1 : B2));

    const int m0 = blockIdx.y * 128, n0 = blockIdx.x * 128;
    const int wm = (warp & 1) * 64, wn = (warp >> 1) * 32;

    const uint32_t sA = smem_u32(As);
    const uint32_t sB = smem_u32(Bs);

    // per-thread ldmatrix row addresses (byte offsets within a buffer)
    uint32_t aoff[4], boff[2];
#pragma unroll
    for (int mt = 0; mt < 4; mt++)
        aoff[mt] = (uint32_t)(((wm + mt * 16 + (mi & 1) * 8 + rr) * GPITCH
                               + (mi >> 1) * 4) * 4);
#pragma unroll
    for (int jj = 0; jj < 2; jj++)
        boff[jj] = (uint32_t)(((wn + (2 * jj + (mi >> 1)) * 8 + rr) * GPITCH
                               + (mi & 1) * 4) * 4);

    float acc[4][4][4];
#pragma unroll
    for (int mt = 0; mt < 4; mt++)
#pragma unroll
        for (int nt = 0; nt < 4; nt++)
#pragma unroll
            for (int r = 0; r < 4; r++) acc[mt][nt][r] = 0.f;

    auto load = [&](int c, int buf) {
        const int k0 = c * KC;
        const uint32_t offA = sA + (uint32_t)buf * 128 * GPITCH * 4;
        const uint32_t offB = sB + (uint32_t)buf * 128 * GPITCH * 4;
#pragma unroll
        for (int i = 0; i < 4; i++) {
            int idx = tid + i * 256;
            int row = idx >> 3, c4 = idx & 7;
            cp16(offA + (row * GPITCH + c4 * 4) * 4,
                 Ap + (size_t)(m0 + row) * DM + k0 + c4 * 4);
            cp16(offB + (row * GPITCH + c4 * 4) * 4,
                 W + (size_t)(n0 + row) * DM + k0 + c4 * 4);
        }
        asm volatile("cp.async.commit_group;" ::: "memory");
    };

    load(0, 0);
    load(1, 1);

    for (int c = 0; c < NCH; ++c) {
        if (c + 1 < NCH) asm volatile("cp.async.wait_group 1;" ::: "memory");
        else             asm volatile("cp.async.wait_group 0;" ::: "memory");
        __syncthreads();

        const uint32_t sAc = sA + (uint32_t)(c & 1) * 128 * GPITCH * 4;
        const uint32_t sBc = sB + (uint32_t)(c & 1) * 128 * GPITCH * 4;
#pragma unroll
        for (int ks = 0; ks < 4; ks++) {
            uint32_t a[4][4], b[4][2];
#pragma unroll
            for (int mt = 0; mt < 4; mt++)
                LDSM4(a[mt][0], a[mt][1], a[mt][2], a[mt][3],
                      sAc + aoff[mt] + (uint32_t)ks * 32);
#pragma unroll
            for (int jj = 0; jj < 2; jj++)
                LDSM4(b[2 * jj][0], b[2 * jj][1], b[2 * jj + 1][0], b[2 * jj + 1][1],
                      sBc + boff[jj] + (uint32_t)ks * 32);
#pragma unroll
            for (int mt = 0; mt < 4; mt++)
#pragma unroll
                for (int nt = 0; nt < 4; nt++)
                    MMA8(acc[mt][nt], a[mt], b[nt]);
        }
        __syncthreads();
        if (c + 2 < NCH) load(c + 2, c & 1);
    }

    const int hh = blockIdx.x;
#pragma unroll
    for (int mt = 0; mt < 4; mt++) {
        int m = m0 + wm + mt * 16 + g;
        int bb = m >> 10, sp = m & 1023;
#pragma unroll
        for (int nt = 0; nt < 4; nt++) {
            int d = wn + nt * 8 + 2 * t;
            int n = n0 + d;
            float b0v = __ldg(bias + n), b1v = __ldg(bias + n + 1);
            float2 v0 = make_float2(acc[mt][nt][0] + b0v, acc[mt][nt][1] + b1v);
            float2 v1 = make_float2(acc[mt][nt][2] + b0v, acc[mt][nt][3] + b1v);
            if (mode) {
                float* dst = outp + (size_t)m * DM + n;
                *(float2*)dst            = v0;
                *(float2*)(dst + 8 * DM) = v1;
            } else if (z == 0) {
                v0.x = rna_tf32(v0.x); v0.y = rna_tf32(v0.y);
                v1.x = rna_tf32(v1.x); v1.y = rna_tf32(v1.y);
                float* dst = g_q + ((size_t)(bb * NH + hh) * S_NEW + sp) * DK + d;
                *(float2*)dst            = v0;
                *(float2*)(dst + 8 * DK) = v1;
            } else {
                float* dst = cache_out
                    + ((size_t)(((z - 1) * BB + bb) * NH + hh) * S_TOT
                       + S_CACHE + sp) * DK + d;
                *(float2*)dst            = v0;
                *(float2*)(dst + 8 * DK) = v1;
            }
        }
    }
}

// ---------------------------------------------------------------------------
// 3) Causal flash attention, BQ=256, warp tile m32, K b-frags via ldmatrix,
//    V fragment tiles dt-paired (one LDS.128 feeds 4 MMAs), P via shuffles.
// ---------------------------------------------------------------------------
// smem floats: Qf 32768 | Kb 2*64*132=16896 | Vf 8*8*132=8448
#define FL_SMEM ((32768 + 16896 + 8448) * 4)   // 232448 B

__global__ __launch_bounds__(256)
void flash_mma_kernel(const float* __restrict__ cache_out) {
    extern __shared__ float smf[];
    float* Qf = smf;                    // [ks16][sub16][lane32][4]
    float* Kb = Qf + 32768;             // [2][64][132] natural
    float* Vf = Kb + 16896;             // [jb8][dp8] tiles of 132 floats

    const int qt = 3 - (int)blockIdx.x;
    const int h  = blockIdx.y;
    const int b  = blockIdx.z;
    const int q0 = qt << 8;
    const int tid  = threadIdx.x;
    const int warp = tid >> 5, lane = tid & 31;
    const int g = lane >> 2, t = lane & 3;
    const int mi = lane >> 3, rr = lane & 7;
    const int base = warp << 5;
    const int subA = warp * 2, subB = warp * 2 + 1;

    const float* Qg = g_q + ((size_t)(b * NH + h) * S_NEW + q0) * DK;
    const float* Kg = cache_out + (size_t)(b * NH + h) * S_TOT * DK;
    const float* Vg = cache_out + (size_t)((BB + b) * NH + h) * S_TOT * DK;

    const uint32_t sKb = smem_u32(Kb);

    // per-thread ldmatrix row addresses for K (byte offset within one K buffer)
    uint32_t koff[4];
#pragma unroll
    for (int jj = 0; jj < 4; jj++)
        koff[jj] = (uint32_t)((((2 * jj + (mi >> 1)) * 8 + rr) * 132
                               + (mi & 1) * 4) * 4);

    auto loadK = [&](int kt) {
        const float* kp = Kg + (size_t)(kt * 64) * DK;
        const uint32_t dstb = sKb + (uint32_t)(kt & 1) * 64 * 132 * 4;
#pragma unroll
        for (int i = 0; i < 8; i++) {
            int idx = tid + i * 256;
            int row = idx >> 5, c16 = (idx & 31) << 2;
            cp16(dstb + (row * 132 + c16) * 4, kp + (size_t)row * DK + c16);
        }
        asm volatile("cp.async.commit_group;" ::: "memory");
    };

    loadK(0);

    // Stage Q in A-fragment order
#pragma unroll
    for (int i = 0; i < 32; i++) {
        int idx = tid + i * 256;
        int row = idx >> 5, c4 = (idx & 31) << 2;
        float4 v = *(const float4*)(Qg + (size_t)row * DK + c4);
        int ks   = c4 >> 3;
        int comp = ((row >> 3) & 1) | ((c4 & 4) >> 1);
        int sub  = row >> 4;
        float* dst = Qf + (((ks * 16 + sub) * 32 + ((row & 7) << 2)) << 2) + comp;
        dst[0] = v.x; dst[4] = v.y; dst[8] = v.z; dst[12] = v.w;
    }

    float O[2][16][4];
    float M[4] = {-1e30f, -1e30f, -1e30f, -1e30f};
    float L[4] = {0.f, 0.f, 0.f, 0.f};
#pragma unroll
    for (int s2 = 0; s2 < 2; s2++)
#pragma unroll
        for (int dt = 0; dt < 16; dt++)
#pragma unroll
            for (int r = 0; r < 4; r++) O[s2][dt][r] = 0.f;

    const float cs = 0.0883883476483184f * 1.4426950408889634f;
    const int ntiles = 52 + 4 * qt;

    const int slA = (lane & 28) | (t >> 1);
    const int slB = slA + 2;
    const bool odd = (t & 1);

    for (int kt = 0; kt < ntiles; ++kt) {
        asm volatile("cp.async.wait_group 0;" ::: "memory");
        __syncthreads();
        if (kt + 1 < ntiles) loadK(kt + 1);

        const uint32_t sKcur = sKb + (uint32_t)(kt & 1) * 64 * 132 * 4;
        const float* vp = Vg + (size_t)(kt * 64) * DK;

        float s[2][8][4];
#pragma unroll
        for (int s2 = 0; s2 < 2; s2++)
#pragma unroll
            for (int nt = 0; nt < 8; nt++)
#pragma unroll
                for (int r = 0; r < 4; r++) s[s2][nt][r] = 0.f;

        // S = Q K^T in 4 quarters; V staged (LDG -> paired-frag STS) between
#pragma unroll
        for (int qtr = 0; qtr < 4; ++qtr) {
            float4 vr0, vr1;
            {
                int idx = tid + (qtr * 2) * 256;
                vr0 = *(const float4*)(vp + (size_t)(idx >> 5) * DK + ((idx & 31) << 2));
                idx += 256;
                vr1 = *(const float4*)(vp + (size_t)(idx >> 5) * DK + ((idx & 31) << 2));
            }
#pragma unroll
            for (int ks = qtr * 4; ks < qtr * 4 + 4; ++ks) {
                float4 aA = *(const float4*)(Qf + (((ks * 16 + subA) * 32 + lane) << 2));
                float4 aB = *(const float4*)(Qf + (((ks * 16 + subB) * 32 + lane) << 2));
                const uint32_t* aAu = reinterpret_cast<const uint32_t*>(&aA);
                const uint32_t* aBu = reinterpret_cast<const uint32_t*>(&aB);
#pragma unroll
                for (int jj = 0; jj < 4; jj++) {
                    uint32_t b0, b1, b2, b3;
                    LDSM4(b0, b1, b2, b3, sKcur + koff[jj] + (uint32_t)ks * 32);
                    uint32_t bA[2] = {b0, b1}, bBv[2] = {b2, b3};
                    MMA8(s[0][2 * jj],     aAu, bA);
                    MMA8(s[1][2 * jj],     aBu, bA);
                    MMA8(s[0][2 * jj + 1], aAu, bBv);
                    MMA8(s[1][2 * jj + 1], aBu, bBv);
                }
            }
            // store V chunk in dt-paired fragment order
#pragma unroll
            for (int j = 0; j < 2; j++) {
                int idx = tid + (qtr * 2 + j) * 256;
                int jr = idx >> 5, d0 = (idx & 31) << 2;
                int jb2 = jr >> 3, tj = jr & 3, compV = (jr >> 2) & 1;
                int dt = d0 >> 3, dp = dt >> 1;
                int lf0 = ((d0 & 7) << 2) + tj;
                float4 vv = j ? vr1 : vr0;
                float* dv = Vf + (jb2 * 8 + dp) * 132 + lf0 * 4
                          + ((dt & 1) << 1) + compV;
                dv[0] = vv.x; dv[16] = vv.y; dv[32] = vv.z; dv[48] = vv.w;
            }
        }

        // ---- online softmax (4 row groups per thread) ----
        const bool domask = (kt * 64 + 63 >= S_CACHE + q0 + base);
#pragma unroll
        for (int sub = 0; sub < 2; sub++)
#pragma unroll
        for (int r = 0; r < 2; r++) {
            const int grp = sub * 2 + r;
            const int rowg = q0 + base + sub * 16 + g + 8 * r;
            float mx = -1e30f;
#pragma unroll
            for (int nt = 0; nt < 8; nt++) {
                float v0 = s[sub][nt][2 * r]     * cs;
                float v1 = s[sub][nt][2 * r + 1] * cs;
                if (domask) {
                    int j = kt * 64 + nt * 8 + 2 * t;
                    if (j     >= S_CACHE + rowg) v0 = -1e30f;
                    if (j + 1 >= S_CACHE + rowg) v1 = -1e30f;
                }
                s[sub][nt][2 * r] = v0; s[sub][nt][2 * r + 1] = v1;
                mx = fmaxf(mx, fmaxf(v0, v1));
            }
            mx = fmaxf(mx, __shfl_xor_sync(0xffffffffu, mx, 1));
            mx = fmaxf(mx, __shfl_xor_sync(0xffffffffu, mx, 2));
            float newM  = fmaxf(M[grp], mx);
            float alpha = exp2f(M[grp] - newM);
            M[grp] = newM;
            float rs = 0.f;
#pragma unroll
            for (int nt = 0; nt < 8; nt++) {
                float p0 = rna_tf32(exp2f(s[sub][nt][2 * r]     - newM));
                float p1 = rna_tf32(exp2f(s[sub][nt][2 * r + 1] - newM));
                rs += p0 + p1;
                s[sub][nt][2 * r] = p0; s[sub][nt][2 * r + 1] = p1;
            }
            rs += __shfl_xor_sync(0xffffffffu, rs, 1);
            rs += __shfl_xor_sync(0xffffffffu, rs, 2);
            L[grp] = L[grp] * alpha + rs;
#pragma unroll
            for (int dt = 0; dt < 16; dt++) {
                O[sub][dt][2 * r]     *= alpha;
                O[sub][dt][2 * r + 1] *= alpha;
            }
        }
        __syncthreads();            // Vf fully written, visible to all warps

        // ---- O += P @ V : P from registers via shuffles, V via LDS.128 ----
#pragma unroll
        for (int jb = 0; jb < 8; jb++) {
            uint32_t aF[2][4];
#pragma unroll
            for (int sub = 0; sub < 2; sub++) {
                float p00 = __shfl_sync(0xffffffffu, s[sub][jb][0], slA);
                float p01 = __shfl_sync(0xffffffffu, s[sub][jb][1], slA);
                float p02 = __shfl_sync(0xffffffffu, s[sub][jb][0], slB);
                float p03 = __shfl_sync(0xffffffffu, s[sub][jb][1], slB);
                float p10 = __shfl_sync(0xffffffffu, s[sub][jb][2], slA);
                float p11 = __shfl_sync(0xffffffffu, s[sub][jb][3], slA);
                float p12 = __shfl_sync(0xffffffffu, s[sub][jb][2], slB);
                float p13 = __shfl_sync(0xffffffffu, s[sub][jb][3], slB);
                aF[sub][0] = __float_as_uint(odd ? p01 : p00);
                aF[sub][1] = __float_as_uint(odd ? p11 : p10);
                aF[sub][2] = __float_as_uint(odd ? p03 : p02);
                aF[sub][3] = __float_as_uint(odd ? p13 : p12);
            }
#pragma unroll
            for (int dp = 0; dp < 8; dp++) {
                float4 bv = *(const float4*)(Vf + (jb * 8 + dp) * 132 + (lane << 2));
                uint32_t bfe[2], bfo[2];
                bfe[0] = __float_as_uint(bv.x); bfe[1] = __float_as_uint(bv.y);
                bfo[0] = __float_as_uint(bv.z); bfo[1] = __float_as_uint(bv.w);
                MMA8(O[0][2 * dp],     aF[0], bfe);
                MMA8(O[1][2 * dp],     aF[1], bfe);
                MMA8(O[0][2 * dp + 1], aF[0], bfo);
                MMA8(O[1][2 * dp + 1], aF[1], bfo);
            }
        }
    }

    // epilogue: normalize + RNA-round + write g_att [b,s,h*dk]
#pragma unroll
    for (int sub = 0; sub < 2; sub++)
#pragma unroll
    for (int r = 0; r < 2; r++) {
        const int grp = sub * 2 + r;
        float inv = 1.f / L[grp];
        int rowg = q0 + base + sub * 16 + g + 8 * r;
        float* dst = g_att + (size_t)(b * S_NEW + rowg) * DM + h * DK;
#pragma unroll
        for (int dt = 0; dt < 16; dt++) {
            float2 v = make_float2(rna_tf32(O[sub][dt][2 * r] * inv),
                                   rna_tf32(O[sub][dt][2 * r + 1] * inv));
            *(float2*)(dst + dt * 8 + 2 * t) = v;
        }
    }
}

// ---------------------------------------------------------------------------
// Launch
// ---------------------------------------------------------------------------
extern "C" void kernel_launch(void* const* d_in, const int* in_sizes, int n_in,
                              void* d_out, int out_size) {
    const float* x     = (const float*)d_in[0];
    const float* cache = (const float*)d_in[1];
    const float* Wq    = (const float*)d_in[2];
    const float* bq    = (const float*)d_in[3];
    const float* Wk    = (const float*)d_in[4];
    const float* bk    = (const float*)d_in[5];
    const float* Wv    = (const float*)d_in[6];
    const float* bv    = (const float*)d_in[7];
    const float* Wo    = (const float*)d_in[8];
    const float* bo    = (const float*)d_in[9];

    float* out       = (float*)d_out;
    float* cache_out = out + (size_t)BB * S_NEW * DM;

    // 0) round x + weights to tf32 (RNA)
    round_kernel<<<4096, 256>>>(x, Wq, Wk, Wv, Wo);

    // 1) copy old cache rows
    {
        int total  = 2 * BB * NH * (S_CACHE * DK / 4);
        int blocks = (total + 255) / 256;
        copy_cache_kernel<<<blocks, 256>>>((const float4*)cache, (float4*)cache_out);
    }

    // 2) fused QKV projections on tensor cores (z=0 Q, z=1 K, z=2 V)
    cudaFuncSetAttribute(gemm_mma_kernel,
                         cudaFuncAttributeMaxDynamicSharedMemorySize, GM_SMEM);
    gemm_mma_kernel<<<dim3(16, 16, 3), 256, GM_SMEM>>>(bq, bk, bv,
                                                       cache_out, nullptr, 0);

    // 3) flash attention on tensor cores (BQ=256, m32, ldmatrix)
    cudaFuncSetAttribute(flash_mma_kernel,
                         cudaFuncAttributeMaxDynamicSharedMemorySize, FL_SMEM);
    flash_mma_kernel<<<dim3(4, NH, BB), 256, FL_SMEM>>>(cache_out);

    // 4) output projection on tensor cores
    gemm_mma_kernel<<<dim3(16, 16, 1), 256, GM_SMEM>>>(bo, nullptr, nullptr,
                                                       nullptr, out, 1);
}

// round 17
// speedup vs baseline: 2.4670x; 2.0908x over previous
#include <cuda_runtime.h>
#include <cuda_fp16.h>
#include <cstdint>

// Problem constants
#define BB      2
#define S_NEW   1024
#define S_CACHE 3072
#define S_TOT   4096
#define NH      16
#define DK      128
#define DM      2048

// Scratch (device globals — no allocation allowed)
__device__ __half g_xh[BB*S_NEW*DM];      // x, fp16
__device__ __half g_wh[4*DM*DM];          // Wq,Wk,Wv,Wo fp16
__device__ __half g_qh[BB*NH*S_NEW*DK];   // Q fp16 [b,h,s,d]
__device__ __half g_kh[BB*NH*S_TOT*DK];   // K cache fp16 (full, incl. new rows)
__device__ __half g_vh[BB*NH*S_TOT*DK];   // V cache fp16
__device__ __half g_atth[BB*S_NEW*DM];    // attention out fp16 [b,s,h*dk]

// ---------------------------------------------------------------------------
// helpers
// ---------------------------------------------------------------------------
__device__ __forceinline__ uint32_t smem_u32(const void* p) {
    uint32_t a;
    asm("{ .reg .u64 t; cvta.to.shared.u64 t, %1; cvt.u32.u64 %0, t; }"
        : "=r"(a) : "l"(p));
    return a;
}
__device__ __forceinline__ void cp16(uint32_t so, const void* gp) {
    asm volatile("cp.async.cg.shared.global [%0], [%1], 16;" :: "r"(so), "l"(gp));
}
__device__ __forceinline__ uint32_t h2(float lo, float hi) {
    __half2 v = __floats2half2_rn(lo, hi);
    return *reinterpret_cast<uint32_t*>(&v);
}

// D(16x8,f32) += A(16x16,f16 row) * B(16x8,f16 col)
#define MMA16(c, a, b)                                                         \
    asm volatile("mma.sync.aligned.m16n8k16.row.col.f32.f16.f16.f32 "         \
        "{%0,%1,%2,%3}, {%4,%5,%6,%7}, {%8,%9}, {%0,%1,%2,%3};"               \
        : "+f"((c)[0]), "+f"((c)[1]), "+f"((c)[2]), "+f"((c)[3])              \
        : "r"((a)[0]), "r"((a)[1]), "r"((a)[2]), "r"((a)[3]),                 \
          "r"((b)[0]), "r"((b)[1]))

#define LDSM4(r0, r1, r2, r3, addr)                                           \
    asm volatile("ldmatrix.sync.aligned.m8n8.x4.shared.b16 {%0,%1,%2,%3}, [%4];" \
        : "=r"(r0), "=r"(r1), "=r"(r2), "=r"(r3) : "r"(addr))

#define LDSM4T(r0, r1, r2, r3, addr)                                          \
    asm volatile("ldmatrix.sync.aligned.m8n8.x4.trans.shared.b16 {%0,%1,%2,%3}, [%4];" \
        : "=r"(r0), "=r"(r1), "=r"(r2), "=r"(r3) : "r"(addr))

// ---------------------------------------------------------------------------
// 0) Convert x and the four weight matrices to fp16 (RN) once.
// ---------------------------------------------------------------------------
__global__ void conv_kernel(const float4* __restrict__ x,
                            const float4* __restrict__ Wq,
                            const float4* __restrict__ Wk,
                            const float4* __restrict__ Wv,
                            const float4* __restrict__ Wo) {
    const int SEG4 = (DM * DM) / 4;          // 1<<20
    int i = blockIdx.x * blockDim.x + threadIdx.x;
    const int stride = gridDim.x * blockDim.x;
    for (; i < 5 * SEG4; i += stride) {
        int seg = i >> 20, o = i & (SEG4 - 1);
        const float4* src = (seg == 0) ? x : (seg == 1) ? Wq
                           : (seg == 2) ? Wk : (seg == 3) ? Wv : Wo;
        float4 v = src[o];
        uint2* dst = (seg == 0) ? (uint2*)g_xh
                                : ((uint2*)g_wh) + (size_t)(seg - 1) * SEG4;
        dst[o] = make_uint2(h2(v.x, v.y), h2(v.z, v.w));
    }
}

// ---------------------------------------------------------------------------
// 1) Copy old cache rows -> cache_out (fp32) AND g_kh/g_vh (fp16)
// ---------------------------------------------------------------------------
__global__ void copy_cache_kernel(const float4* __restrict__ src,
                                  float4* __restrict__ dst) {
    int i = blockIdx.x * blockDim.x + threadIdx.x;
    const int per   = S_CACHE * DK / 4;      // 98304
    const int total = 2 * BB * NH * per;
    if (i < total) {
        int c = i / per;
        int w = i - c * per;
        float4 v = src[i];
        dst[(size_t)c * (S_TOT * DK / 4) + w] = v;
        int kv = c >> 5;                     // BB*NH = 32
        int bh = c & 31;
        __half* hp = (kv ? g_vh : g_kh) + (size_t)bh * S_TOT * DK + (size_t)w * 4;
        *(uint2*)hp = make_uint2(h2(v.x, v.y), h2(v.z, v.w));
    }
}

// ---------------------------------------------------------------------------
// 2/4) fp16 tensor-core GEMM: Y[M,N] = A[M,K] @ W[N,K]^T + bias.
//      128x128 tile, 8 warps (2Mx4N), KC=64, double-buffered cp.async,
//      all fragments via ldmatrix.
// ---------------------------------------------------------------------------
#define KC      64
#define GP      72                         // pitch in halves (144B, conflict-free)
#define NCH     (DM / KC)                  // 32
#define GM_SMEM (2 * 2 * 128 * GP * 2)     // 73728 B

__global__ __launch_bounds__(256, 2)
void gemm_mma_kernel(const float* __restrict__ B0,
                     const float* __restrict__ B1,
                     const float* __restrict__ B2,
                     float* __restrict__ cache_out,
                     float* __restrict__ outp,
                     int mode) {
    extern __shared__ __half gsm[];
    __half* As = gsm;                        // [2][128*GP]
    __half* Bs = gsm + 2 * 128 * GP;

    const int tid = threadIdx.x;
    const int warp = tid >> 5, lane = tid & 31;
    const int g = lane >> 2, t = lane & 3;
    const int z = blockIdx.z;

    const __half* Ap = mode ? g_atth : g_xh;
    const __half* W  = g_wh + (size_t)(mode ? 3 : z) * DM * DM;
    const float* bias = mode ? B0 : (z == 0 ? B0 : (z == 1 ? B1 : B2));

    const int m0 = blockIdx.y * 128, n0 = blockIdx.x * 128;
    const int wm = (warp & 1) * 64, wn = (warp >> 1) * 32;

    const uint32_t sA = smem_u32(As);
    const uint32_t sB = smem_u32(Bs);

    // ldmatrix byte offsets within one buffer
    uint32_t aoff[4], boff[2];
#pragma unroll
    for (int mt = 0; mt < 4; mt++)
        aoff[mt] = (uint32_t)(((wm + mt * 16 + (lane & 15)) * GP
                               + (lane >> 4) * 8) * 2);
#pragma unroll
    for (int jj = 0; jj < 2; jj++)
        boff[jj] = (uint32_t)(((wn + jj * 16 + ((lane >> 4) << 3) + (lane & 7)) * GP
                               + ((lane >> 3) & 1) * 8) * 2);

    float acc[4][4][4];
#pragma unroll
    for (int mt = 0; mt < 4; mt++)
#pragma unroll
        for (int nt = 0; nt < 4; nt++)
#pragma unroll
            for (int r = 0; r < 4; r++) acc[mt][nt][r] = 0.f;

    auto load = [&](int c, int buf) {
        const int k0 = c * KC;
        const uint32_t offA = sA + (uint32_t)buf * 128 * GP * 2;
        const uint32_t offB = sB + (uint32_t)buf * 128 * GP * 2;
#pragma unroll
        for (int i = 0; i < 4; i++) {
            int idx = tid + i * 256;         // 0..1023
            int row = idx >> 3, c8 = idx & 7;
            cp16(offA + (row * GP + c8 * 8) * 2,
                 Ap + (size_t)(m0 + row) * DM + k0 + c8 * 8);
            cp16(offB + (row * GP + c8 * 8) * 2,
                 W + (size_t)(n0 + row) * DM + k0 + c8 * 8);
        }
        asm volatile("cp.async.commit_group;" ::: "memory");
    };

    load(0, 0);
    load(1, 1);

    for (int c = 0; c < NCH; ++c) {
        if (c + 1 < NCH) asm volatile("cp.async.wait_group 1;" ::: "memory");
        else             asm volatile("cp.async.wait_group 0;" ::: "memory");
        __syncthreads();

        const uint32_t bo = (uint32_t)(c & 1) * 128 * GP * 2;
#pragma unroll
        for (int ks = 0; ks < 4; ks++) {     // k16 steps
            uint32_t a[4][4], b[4][2];
#pragma unroll
            for (int mt = 0; mt < 4; mt++)
                LDSM4(a[mt][0], a[mt][1], a[mt][2], a[mt][3],
                      sA + bo + aoff[mt] + (uint32_t)ks * 32);
#pragma unroll
            for (int jj = 0; jj < 2; jj++)
                LDSM4(b[2 * jj][0], b[2 * jj][1], b[2 * jj + 1][0], b[2 * jj + 1][1],
                      sB + bo + boff[jj] + (uint32_t)ks * 32);
#pragma unroll
            for (int mt = 0; mt < 4; mt++)
#pragma unroll
                for (int nt = 0; nt < 4; nt++)
                    MMA16(acc[mt][nt], a[mt], b[nt]);
        }
        __syncthreads();
        if (c + 2 < NCH) load(c + 2, c & 1);
    }

    const int hh = blockIdx.x;
#pragma unroll
    for (int mt = 0; mt < 4; mt++) {
        int m = m0 + wm + mt * 16 + g;
        int bb = m >> 10, sp = m & 1023;
#pragma unroll
        for (int nt = 0; nt < 4; nt++) {
            int d = wn + nt * 8 + 2 * t;
            int n = n0 + d;
            float b0v = __ldg(bias + n), b1v = __ldg(bias + n + 1);
            float2 v0 = make_float2(acc[mt][nt][0] + b0v, acc[mt][nt][1] + b1v);
            float2 v1 = make_float2(acc[mt][nt][2] + b0v, acc[mt][nt][3] + b1v);
            if (mode) {
                float* dst = outp + (size_t)m * DM + n;
                *(float2*)dst            = v0;
                *(float2*)(dst + 8 * DM) = v1;
            } else if (z == 0) {
                __half* hd = g_qh + ((size_t)(bb * NH + hh) * S_NEW + sp) * DK + d;
                *(uint32_t*)hd            = h2(v0.x, v0.y);
                *(uint32_t*)(hd + 8 * DK) = h2(v1.x, v1.y);
            } else {
                float* dst = cache_out
                    + ((size_t)(((z - 1) * BB + bb) * NH + hh) * S_TOT
                       + S_CACHE + sp) * DK + d;
                *(float2*)dst            = v0;
                *(float2*)(dst + 8 * DK) = v1;
                __half* hd = (z == 1 ? g_kh : g_vh)
                    + ((size_t)(bb * NH + hh) * S_TOT + S_CACHE + sp) * DK + d;
                *(uint32_t*)hd            = h2(v0.x, v0.y);
                *(uint32_t*)(hd + 8 * DK) = h2(v1.x, v1.y);
            }
        }
    }
}

// ---------------------------------------------------------------------------
// 3) Causal flash attention, fp16 MMA. BQ=256, warp tile m32, K and V both
//    cp.async double-buffered, P->A-fragments directly from registers
//    (fp16 k16 fragment layout == S accumulator layout; zero shuffles).
// ---------------------------------------------------------------------------
#define FP      136                        // pitch in halves (272B, conflict-free)
#define FL_SMEM ((256 * FP + 2 * 64 * FP + 2 * 64 * FP) * 2)   // 139264 B

__global__ __launch_bounds__(256)
void flash_mma_kernel() {
    extern __shared__ __half smh[];
    __half* Qs = smh;                       // [256][FP]
    __half* Kb = Qs + 256 * FP;             // [2][64][FP]
    __half* Vb = Kb + 2 * 64 * FP;          // [2][64][FP]

    const int qt = 3 - (int)blockIdx.x;     // longest tiles first
    const int h  = blockIdx.y;
    const int b  = blockIdx.z;
    const int q0 = qt << 8;
    const int tid  = threadIdx.x;
    const int warp = tid >> 5, lane = tid & 31;
    const int g = lane >> 2, t = lane & 3;
    const int base = warp << 5;             // warp's 32 query rows

    const __half* Qg = g_qh + ((size_t)(b * NH + h) * S_NEW + q0) * DK;
    const __half* Kg = g_kh + (size_t)(b * NH + h) * S_TOT * DK;
    const __half* Vg = g_vh + (size_t)(b * NH + h) * S_TOT * DK;

    const uint32_t sQ = smem_u32(Qs);
    const uint32_t sK = smem_u32(Kb);
    const uint32_t sV = smem_u32(Vb);

    auto loadKV = [&](int kt) {
        const __half* kp = Kg + (size_t)(kt * 64) * DK;
        const __half* vp = Vg + (size_t)(kt * 64) * DK;
        const uint32_t bo = (uint32_t)(kt & 1) * 64 * FP * 2;
#pragma unroll
        for (int i = 0; i < 4; i++) {
            int idx = tid + i * 256;         // 0..1023
            int row = idx >> 4, c8 = idx & 15;
            cp16(sK + bo + (row * FP + c8 * 8) * 2, kp + (size_t)row * DK + c8 * 8);
            cp16(sV + bo + (row * FP + c8 * 8) * 2, vp + (size_t)row * DK + c8 * 8);
        }
        asm volatile("cp.async.commit_group;" ::: "memory");
    };

    // Q tile (256 x 128 halves) via cp.async
#pragma unroll
    for (int i = 0; i < 16; i++) {
        int idx = tid + i * 256;
        int row = idx >> 4, c8 = idx & 15;
        cp16(sQ + (row * FP + c8 * 8) * 2, Qg + (size_t)row * DK + c8 * 8);
    }
    asm volatile("cp.async.commit_group;" ::: "memory");
    loadKV(0);

    // fragment addresses (bytes)
    uint32_t qoff[2], koff[4], voff[4];
#pragma unroll
    for (int sub = 0; sub < 2; sub++)
        qoff[sub] = (uint32_t)(((base + sub * 16 + (lane & 15)) * FP
                                + (lane >> 4) * 8) * 2);
#pragma unroll
    for (int np = 0; np < 4; np++)
        koff[np] = (uint32_t)(((np * 16 + ((lane >> 4) << 3) + (lane & 7)) * FP
                               + ((lane >> 3) & 1) * 8) * 2);
#pragma unroll
    for (int jb = 0; jb < 4; jb++)
        voff[jb] = (uint32_t)(((jb * 16 + (lane & 15)) * FP
                               + ((lane >> 4) << 3)) * 2);

    float O[2][16][4];
    float M[4] = {-1e30f, -1e30f, -1e30f, -1e30f};
    float L[4] = {0.f, 0.f, 0.f, 0.f};
#pragma unroll
    for (int s2 = 0; s2 < 2; s2++)
#pragma unroll
        for (int dt = 0; dt < 16; dt++)
#pragma unroll
            for (int r = 0; r < 4; r++) O[s2][dt][r] = 0.f;

    const float cs = 0.0883883476483184f * 1.4426950408889634f; // 1/sqrt(128)*log2e
    const int ntiles = 52 + 4 * qt;

    for (int kt = 0; kt < ntiles; ++kt) {
        asm volatile("cp.async.wait_group 0;" ::: "memory");
        __syncthreads();
        if (kt + 1 < ntiles) loadKV(kt + 1);   // runs under the MMAs below

        const uint32_t bo = (uint32_t)(kt & 1) * 64 * FP * 2;

        float s[2][8][4];
#pragma unroll
        for (int s2 = 0; s2 < 2; s2++)
#pragma unroll
            for (int nt = 0; nt < 8; nt++)
#pragma unroll
                for (int r = 0; r < 4; r++) s[s2][nt][r] = 0.f;

        // ---- S = Q @ K^T (8 k16 steps) ----
#pragma unroll
        for (int ks = 0; ks < 8; ks++) {
            uint32_t aA[4], aB[4];
            LDSM4(aA[0], aA[1], aA[2], aA[3], sQ + qoff[0] + (uint32_t)ks * 32);
            LDSM4(aB[0], aB[1], aB[2], aB[3], sQ + qoff[1] + (uint32_t)ks * 32);
#pragma unroll
            for (int np = 0; np < 4; np++) {
                uint32_t b0[2], b1[2];
                LDSM4(b0[0], b0[1], b1[0], b1[1],
                      sK + bo + koff[np] + (uint32_t)ks * 32);
                MMA16(s[0][2 * np],     aA, b0);
                MMA16(s[1][2 * np],     aB, b0);
                MMA16(s[0][2 * np + 1], aA, b1);
                MMA16(s[1][2 * np + 1], aB, b1);
            }
        }

        // ---- online softmax; P packed to fp16 fragments in registers ----
        const bool domask = (kt * 64 + 63 >= S_CACHE + q0 + base);
        uint32_t Ph[2][8][2];
#pragma unroll
        for (int sub = 0; sub < 2; sub++)
#pragma unroll
        for (int r = 0; r < 2; r++) {
            const int grp = sub * 2 + r;
            const int rowg = q0 + base + sub * 16 + g + 8 * r;
            float mx = -1e30f;
#pragma unroll
            for (int nt = 0; nt < 8; nt++) {
                float v0 = s[sub][nt][2 * r]     * cs;
                float v1 = s[sub][nt][2 * r + 1] * cs;
                if (domask) {
                    int j = kt * 64 + nt * 8 + 2 * t;
                    if (j     >= S_CACHE + rowg) v0 = -1e30f;
                    if (j + 1 >= S_CACHE + rowg) v1 = -1e30f;
                }
                s[sub][nt][2 * r] = v0; s[sub][nt][2 * r + 1] = v1;
                mx = fmaxf(mx, fmaxf(v0, v1));
            }
            mx = fmaxf(mx, __shfl_xor_sync(0xffffffffu, mx, 1));
            mx = fmaxf(mx, __shfl_xor_sync(0xffffffffu, mx, 2));
            float newM  = fmaxf(M[grp], mx);
            float alpha = exp2f(M[grp] - newM);
            M[grp] = newM;
            float rs = 0.f;
#pragma unroll
            for (int nt = 0; nt < 8; nt++) {
                float p0 = exp2f(s[sub][nt][2 * r]     - newM);
                float p1 = exp2f(s[sub][nt][2 * r + 1] - newM);
                rs += p0 + p1;
                Ph[sub][nt][r] = h2(p0, p1);
            }
            rs += __shfl_xor_sync(0xffffffffu, rs, 1);
            rs += __shfl_xor_sync(0xffffffffu, rs, 2);
            L[grp] = L[grp] * alpha + rs;
#pragma unroll
            for (int dt = 0; dt < 16; dt++) {
                O[sub][dt][2 * r]     *= alpha;
                O[sub][dt][2 * r + 1] *= alpha;
            }
        }

        // ---- O += P @ V (4 k16 steps over j) ----
#pragma unroll
        for (int jb = 0; jb < 4; jb++) {
            uint32_t aF0[4] = {Ph[0][2 * jb][0], Ph[0][2 * jb][1],
                               Ph[0][2 * jb + 1][0], Ph[0][2 * jb + 1][1]};
            uint32_t aF1[4] = {Ph[1][2 * jb][0], Ph[1][2 * jb][1],
                               Ph[1][2 * jb + 1][0], Ph[1][2 * jb + 1][1]};
#pragma unroll
            for (int dp = 0; dp < 8; dp++) {
                uint32_t b0[2], b1[2];
                LDSM4T(b0[0], b0[1], b1[0], b1[1],
                       sV + bo + voff[jb] + (uint32_t)dp * 32);
                MMA16(O[0][2 * dp],     aF0, b0);
                MMA16(O[1][2 * dp],     aF1, b0);
                MMA16(O[0][2 * dp + 1], aF0, b1);
                MMA16(O[1][2 * dp + 1], aF1, b1);
            }
        }
    }

    // epilogue: normalize + fp16 write to g_atth [b,s,h*dk]
#pragma unroll
    for (int sub = 0; sub < 2; sub++)
#pragma unroll
    for (int r = 0; r < 2; r++) {
        const int grp = sub * 2 + r;
        float inv = 1.f / L[grp];
        int rowg = q0 + base + sub * 16 + g + 8 * r;
        __half* dst = g_atth + (size_t)(b * S_NEW + rowg) * DM + h * DK;
#pragma unroll
        for (int dt = 0; dt < 16; dt++)
            *(uint32_t*)(dst + dt * 8 + 2 * t) =
                h2(O[sub][dt][2 * r] * inv, O[sub][dt][2 * r + 1] * inv);
    }
}

// ---------------------------------------------------------------------------
// Launch
// ---------------------------------------------------------------------------
extern "C" void kernel_launch(void* const* d_in, const int* in_sizes, int n_in,
                              void* d_out, int out_size) {
    const float* x     = (const float*)d_in[0];
    const float* cache = (const float*)d_in[1];
    const float* Wq    = (const float*)d_in[2];
    const float* bq    = (const float*)d_in[3];
    const float* Wk    = (const float*)d_in[4];
    const float* bk    = (const float*)d_in[5];
    const float* Wv    = (const float*)d_in[6];
    const float* bv    = (const float*)d_in[7];
    const float* Wo    = (const float*)d_in[8];
    const float* bo    = (const float*)d_in[9];

    float* out       = (float*)d_out;
    float* cache_out = out + (size_t)BB * S_NEW * DM;

    // 0) convert x + weights to fp16
    conv_kernel<<<8192, 256>>>((const float4*)x, (const float4*)Wq,
                               (const float4*)Wk, (const float4*)Wv,
                               (const float4*)Wo);

    // 1) copy old cache rows (fp32 out + fp16 copies)
    {
        int total  = 2 * BB * NH * (S_CACHE * DK / 4);
        int blocks = (total + 255) / 256;
        copy_cache_kernel<<<blocks, 256>>>((const float4*)cache, (float4*)cache_out);
    }

    // 2) fused QKV projections (z=0 Q, z=1 K, z=2 V)
    cudaFuncSetAttribute(gemm_mma_kernel,
                         cudaFuncAttributeMaxDynamicSharedMemorySize, GM_SMEM);
    gemm_mma_kernel<<<dim3(16, 16, 3), 256, GM_SMEM>>>(bq, bk, bv,
                                                       cache_out, nullptr, 0);

    // 3) flash attention (fp16 MMA, BQ=256)
    cudaFuncSetAttribute(flash_mma_kernel,
                         cudaFuncAttributeMaxDynamicSharedMemorySize, FL_SMEM);
    flash_mma_kernel<<<dim3(4, NH, BB), 256, FL_SMEM>>>();

    // 4) output projection
    gemm_mma_kernel<<<dim3(16, 16, 1), 256, GM_SMEM>>>(bo, nullptr, nullptr,
                                                       nullptr, out, 1);
}